// round 1
// baseline (speedup 1.0000x reference)
#include <cuda_runtime.h>
#include <math.h>

// Problem constants
#define Bc   2
#define Sc   2048
#define Dc   1024
#define Hc   16
#define DKc  64
#define Mc   (Bc*Sc)   // 4096 rows for the projections

// Scratch (allocation-free rule: __device__ globals)
__device__ float g_Q[Bc*Hc*Sc*DKc];     // [B,H,S,DK]
__device__ float g_K[Bc*Hc*Sc*DKc];
__device__ float g_V[Bc*Hc*Sc*DKc];
__device__ float g_ctx[Bc*Sc*Dc];       // merged-head [B,S,D]

// ---------------------------------------------------------------------------
// GEMM: C = A @ W^T + bias.  A:[M,1024] row-major, W:[1024,1024] row-major.
// 64x64 block tile, 256 threads, 4x4 register tile, k-tile 16.
// split_head=1 -> scatter output into [B,H,S,DK] layout.
// ---------------------------------------------------------------------------
__global__ __launch_bounds__(256) void gemm_bias_kernel(
    const float* __restrict__ A, const float* __restrict__ W,
    const float* __restrict__ bias, float* __restrict__ C, int split_head)
{
    __shared__ float As[16][68];   // [k][m]
    __shared__ float Ws[16][68];   // [k][n]

    const int tid = threadIdx.x;
    const int tx  = tid & 15;          // 0..15 (n direction)
    const int ty  = tid >> 4;          // 0..15 (m direction)
    const int m0  = blockIdx.y << 6;
    const int n0  = blockIdx.x << 6;

    // load mapping: each thread loads one float4 of A and W per k-step
    const int lm = tid >> 2;           // 0..63 row within tile
    const int lk = (tid & 3) << 2;     // 0,4,8,12 k offset

    float acc[4][4];
#pragma unroll
    for (int i = 0; i < 4; i++)
#pragma unroll
        for (int j = 0; j < 4; j++) acc[i][j] = 0.f;

    const float* Aptr = A + (size_t)(m0 + lm) * Dc + lk;
    const float* Wptr = W + (size_t)(n0 + lm) * Dc + lk;

    for (int k0 = 0; k0 < Dc; k0 += 16) {
        float4 a4 = *(const float4*)(Aptr + k0);
        float4 w4 = *(const float4*)(Wptr + k0);
        As[lk + 0][lm] = a4.x; As[lk + 1][lm] = a4.y;
        As[lk + 2][lm] = a4.z; As[lk + 3][lm] = a4.w;
        Ws[lk + 0][lm] = w4.x; Ws[lk + 1][lm] = w4.y;
        Ws[lk + 2][lm] = w4.z; Ws[lk + 3][lm] = w4.w;
        __syncthreads();
#pragma unroll
        for (int kk = 0; kk < 16; kk++) {
            float4 av = *(const float4*)&As[kk][ty << 2];
            float4 wv = *(const float4*)&Ws[kk][tx << 2];
            float a_[4] = {av.x, av.y, av.z, av.w};
            float w_[4] = {wv.x, wv.y, wv.z, wv.w};
#pragma unroll
            for (int i = 0; i < 4; i++)
#pragma unroll
                for (int j = 0; j < 4; j++)
                    acc[i][j] += a_[i] * w_[j];
        }
        __syncthreads();
    }

#pragma unroll
    for (int i = 0; i < 4; i++) {
        const int m = m0 + (ty << 2) + i;
#pragma unroll
        for (int j = 0; j < 4; j++) {
            const int n = n0 + (tx << 2) + j;
            const float v = acc[i][j] + bias[n];
            if (split_head) {
                const int b = m >> 11, s = m & (Sc - 1);
                const int h = n >> 6,  d = n & (DKc - 1);
                C[((size_t)(b * Hc + h) * Sc + s) * DKc + d] = v;
            } else {
                C[(size_t)m * Dc + n] = v;
            }
        }
    }
}

// ---------------------------------------------------------------------------
// Flash attention (fp32). One CTA = 64 query rows of one (b,h).
// K/V tiles of 32 rows. Online softmax. Output written merged-head [B,S,D].
// Static smem: 17.4 + 9.2 + 8.7 + 9.2 = 44.5 KB (< 48 KB static limit).
// ---------------------------------------------------------------------------
__global__ __launch_bounds__(256) void attn_kernel(
    const float* __restrict__ Q, const float* __restrict__ K,
    const float* __restrict__ V, float* __restrict__ ctx)
{
    __shared__ float Qst[DKc][68];   // [d][r]  r = 0..63
    __shared__ float Kst[DKc][36];   // [d][c]  c = 0..31
    __shared__ float Vs [32][68];    // [c][dv]
    __shared__ float Ps [64][36];    // [r][c]

    const int tid = threadIdx.x;
    const int tx  = tid & 15;        // 0..15
    const int ty  = tid >> 4;        // 0..15
    const int bh  = blockIdx.y;      // 0..31
    const int q0  = blockIdx.x << 6;

    const float* Qb = Q + (size_t)bh * Sc * DKc;
    const float* Kb = K + (size_t)bh * Sc * DKc;
    const float* Vb = V + (size_t)bh * Sc * DKc;

    // Load Q tile transposed (once)
    {
        const int r  = tid >> 2;      // 0..63
        const int c4 = tid & 3;       // float4 group base
#pragma unroll
        for (int t = 0; t < 4; t++) {
            const int d4 = c4 + (t << 2);   // 0..15
            float4 v = *(const float4*)(Qb + (size_t)(q0 + r) * DKc + (d4 << 2));
            Qst[(d4 << 2) + 0][r] = v.x; Qst[(d4 << 2) + 1][r] = v.y;
            Qst[(d4 << 2) + 2][r] = v.z; Qst[(d4 << 2) + 3][r] = v.w;
        }
    }

    const int r0 = ty << 2;          // my 4 query rows within tile
    const int c0 = tx << 1;          // my 2 key cols within k-tile

    float m_i[4], l_i[4], O[4][4];
#pragma unroll
    for (int i = 0; i < 4; i++) {
        m_i[i] = -1e30f; l_i[i] = 0.f;
#pragma unroll
        for (int j = 0; j < 4; j++) O[i][j] = 0.f;
    }

    const float scale = 0.125f;      // 1/sqrt(64)

    for (int kt = 0; kt < Sc; kt += 32) {
        // Load K (transposed) and V tiles (32 rows x 64)
        {
            const int r  = tid >> 3;   // 0..31
            const int c4 = tid & 7;    // 0..7
#pragma unroll
            for (int t = 0; t < 2; t++) {
                const int d4 = c4 + (t << 3);   // 0..15
                float4 kv = *(const float4*)(Kb + (size_t)(kt + r) * DKc + (d4 << 2));
                Kst[(d4 << 2) + 0][r] = kv.x; Kst[(d4 << 2) + 1][r] = kv.y;
                Kst[(d4 << 2) + 2][r] = kv.z; Kst[(d4 << 2) + 3][r] = kv.w;
                float4 vv = *(const float4*)(Vb + (size_t)(kt + r) * DKc + (d4 << 2));
                *(float4*)&Vs[r][d4 << 2] = vv;
            }
        }
        __syncthreads();

        // Scores: s[i][jc], rows r0.., cols c0..  (64 x 32 tile over 256 thr)
        float s[4][2];
#pragma unroll
        for (int i = 0; i < 4; i++) { s[i][0] = 0.f; s[i][1] = 0.f; }
#pragma unroll 8
        for (int d = 0; d < DKc; d++) {
            float4 qv = *(const float4*)&Qst[d][r0];
            float k0v = Kst[d][c0];
            float k1v = Kst[d][c0 + 1];
            s[0][0] += qv.x * k0v; s[0][1] += qv.x * k1v;
            s[1][0] += qv.y * k0v; s[1][1] += qv.y * k1v;
            s[2][0] += qv.z * k0v; s[2][1] += qv.z * k1v;
            s[3][0] += qv.w * k0v; s[3][1] += qv.w * k1v;
        }

        // Online softmax update per row (reduce across the 16 tx lanes)
#pragma unroll
        for (int i = 0; i < 4; i++) {
            s[i][0] *= scale; s[i][1] *= scale;
            float mx = fmaxf(s[i][0], s[i][1]);
#pragma unroll
            for (int o = 1; o < 16; o <<= 1)
                mx = fmaxf(mx, __shfl_xor_sync(0xffffffffu, mx, o));
            const float mnew  = fmaxf(m_i[i], mx);
            const float factor = __expf(m_i[i] - mnew);
            const float p0 = __expf(s[i][0] - mnew);
            const float p1 = __expf(s[i][1] - mnew);
            float rs = p0 + p1;
#pragma unroll
            for (int o = 1; o < 16; o <<= 1)
                rs += __shfl_xor_sync(0xffffffffu, rs, o);
            l_i[i] = l_i[i] * factor + rs;
            m_i[i] = mnew;
            Ps[r0 + i][c0]     = p0;
            Ps[r0 + i][c0 + 1] = p1;
#pragma unroll
            for (int j = 0; j < 4; j++) O[i][j] *= factor;
        }
        __syncthreads();

        // PV: O[i][j] += sum_c Ps[r0+i][c] * Vs[c][tx*4+j]
#pragma unroll 4
        for (int c = 0; c < 32; c++) {
            float4 vv = *(const float4*)&Vs[c][tx << 2];
            float p0 = Ps[r0 + 0][c];
            float p1 = Ps[r0 + 1][c];
            float p2 = Ps[r0 + 2][c];
            float p3 = Ps[r0 + 3][c];
            O[0][0] += p0 * vv.x; O[0][1] += p0 * vv.y; O[0][2] += p0 * vv.z; O[0][3] += p0 * vv.w;
            O[1][0] += p1 * vv.x; O[1][1] += p1 * vv.y; O[1][2] += p1 * vv.z; O[1][3] += p1 * vv.w;
            O[2][0] += p2 * vv.x; O[2][1] += p2 * vv.y; O[2][2] += p2 * vv.z; O[2][3] += p2 * vv.w;
            O[3][0] += p3 * vv.x; O[3][1] += p3 * vv.y; O[3][2] += p3 * vv.z; O[3][3] += p3 * vv.w;
        }
        __syncthreads();
    }

    // Epilogue: normalize and write merged-head ctx [B,S,D]
    const int b = bh >> 4, h = bh & (Hc - 1);
#pragma unroll
    for (int i = 0; i < 4; i++) {
        const float inv = 1.f / l_i[i];
        const int srow = q0 + r0 + i;
        float* dst = ctx + ((size_t)(b * Sc + srow) * Dc) + h * DKc + (tx << 2);
        float4 o4;
        o4.x = O[i][0] * inv; o4.y = O[i][1] * inv;
        o4.z = O[i][2] * inv; o4.w = O[i][3] * inv;
        *(float4*)dst = o4;
    }
}

// ---------------------------------------------------------------------------
// Launch
// ---------------------------------------------------------------------------
extern "C" void kernel_launch(void* const* d_in, const int* in_sizes, int n_in,
                              void* d_out, int out_size)
{
    const float* query = (const float*)d_in[0];
    const float* key   = (const float*)d_in[1];
    const float* value = (const float*)d_in[2];
    const float* Wq    = (const float*)d_in[3];
    const float* bq    = (const float*)d_in[4];
    const float* Wk    = (const float*)d_in[5];
    const float* bk    = (const float*)d_in[6];
    const float* Wv    = (const float*)d_in[7];
    const float* bv    = (const float*)d_in[8];
    const float* Wo    = (const float*)d_in[9];
    const float* bo    = (const float*)d_in[10];
    float* out = (float*)d_out;

    float *qbuf, *kbuf, *vbuf, *cbuf;
    cudaGetSymbolAddress((void**)&qbuf, g_Q);
    cudaGetSymbolAddress((void**)&kbuf, g_K);
    cudaGetSymbolAddress((void**)&vbuf, g_V);
    cudaGetSymbolAddress((void**)&cbuf, g_ctx);

    dim3 gblk(256);
    dim3 ggrid(Dc / 64, Mc / 64);   // (16, 64)

    gemm_bias_kernel<<<ggrid, gblk>>>(query, Wq, bq, qbuf, 1);
    gemm_bias_kernel<<<ggrid, gblk>>>(key,   Wk, bk, kbuf, 1);
    gemm_bias_kernel<<<ggrid, gblk>>>(value, Wv, bv, vbuf, 1);

    dim3 agrid(Sc / 64, Bc * Hc);   // (32, 32)
    attn_kernel<<<agrid, gblk>>>(qbuf, kbuf, vbuf, cbuf);

    gemm_bias_kernel<<<ggrid, gblk>>>(cbuf, Wo, bo, out, 0);
}

// round 3
// speedup vs baseline: 3.1714x; 3.1714x over previous
#include <cuda_runtime.h>
#include <cstdint>
#include <math.h>

// Problem constants
#define Bc2  2
#define Sc   2048
#define Dc   1024
#define Hc   16
#define DKc  64
#define Mc   (Bc2*Sc)   // 4096 rows for the projections

// Scratch (allocation-free rule: __device__ globals)
__device__ float g_Q[Bc2*Hc*Sc*DKc];    // [B,H,S,DK]
__device__ float g_K[Bc2*Hc*Sc*DKc];
__device__ float g_V[Bc2*Hc*Sc*DKc];
__device__ float g_ctx[Bc2*Sc*Dc];      // merged-head [B,S,D]

// ---------------------------------------------------------------------------
// tf32 helpers (mma.sync is supported at plain compute_103 — tcgen05 is NOT)
// ---------------------------------------------------------------------------
__device__ __forceinline__ uint32_t tf32u(float x) {
    uint32_t u;
    asm("cvt.rna.tf32.f32 %0, %1;" : "=r"(u) : "f"(x));
    return u;
}

// C += A(16x8) * B(8x8), tf32 inputs, fp32 accum.
// A frag: a0=(g,t) a1=(g+8,t) a2=(g,t+4) a3=(g+8,t+4); g=lane/4, t=lane%4
// B frag: b0=(k=t,n=g) b1=(k=t+4,n=g)
// C frag: c0=(g,2t) c1=(g,2t+1) c2=(g+8,2t) c3=(g+8,2t+1)
__device__ __forceinline__ void mma8(float c[4], const uint32_t a[4],
                                     uint32_t b0, uint32_t b1) {
    asm volatile(
        "mma.sync.aligned.m16n8k8.row.col.f32.tf32.tf32.f32 "
        "{%0,%1,%2,%3},{%4,%5,%6,%7},{%8,%9},{%0,%1,%2,%3};"
        : "+f"(c[0]), "+f"(c[1]), "+f"(c[2]), "+f"(c[3])
        : "r"(a[0]), "r"(a[1]), "r"(a[2]), "r"(a[3]), "r"(b0), "r"(b1));
}

// ===========================================================================
// GEMM: C = A @ W^T + bias.  A:[M,1024], W:[1024,1024] row-major fp32.
// CTA 128x128, 256 threads (8 warps = 2m x 4n, warp tile 64x32), k-chunk 32.
// ===========================================================================
#define GSTR 36   // smem row stride in words (32 + 4 pad)

__global__ __launch_bounds__(256) void gemm_mma(
    const float* __restrict__ A, const float* __restrict__ W,
    const float* __restrict__ bias, float* __restrict__ C, int split_head)
{
    __shared__ uint32_t sA[128 * GSTR];   // 18.4 KB
    __shared__ uint32_t sB[128 * GSTR];

    const int tid  = threadIdx.x;
    const int lane = tid & 31;
    const int wid  = tid >> 5;
    const int wm   = wid & 1;       // 0..1  (m direction, 64 rows each)
    const int wn   = wid >> 1;      // 0..3  (n direction, 32 cols each)
    const int g    = lane >> 2;
    const int t    = lane & 3;
    const int m0   = blockIdx.y << 7;
    const int n0   = blockIdx.x << 7;

    float acc[4][4][4];
#pragma unroll
    for (int mi = 0; mi < 4; mi++)
#pragma unroll
        for (int nj = 0; nj < 4; nj++)
#pragma unroll
            for (int r = 0; r < 4; r++) acc[mi][nj][r] = 0.f;

    // staging map: 1024 float4 per matrix per chunk; 4 per thread
    int rowv[4], qv[4];
#pragma unroll
    for (int j = 0; j < 4; j++) {
        int v = tid + (j << 8);
        rowv[j] = v >> 3;       // 0..127
        qv[j]   = v & 7;        // float4 index within 32-float row
    }

    // prefetch chunk 0
    float4 pa[4], pb[4];
#pragma unroll
    for (int j = 0; j < 4; j++) {
        pa[j] = *(const float4*)(A + (size_t)(m0 + rowv[j]) * Dc + (qv[j] << 2));
        pb[j] = *(const float4*)(W + (size_t)(n0 + rowv[j]) * Dc + (qv[j] << 2));
    }

    for (int kc = 0; kc < 32; kc++) {
        // STS current chunk (cvt to tf32 in regs, vector store)
#pragma unroll
        for (int j = 0; j < 4; j++) {
            const int wb = rowv[j] * GSTR + (qv[j] << 2);
            uint4 ua, ub;
            ua.x = tf32u(pa[j].x); ua.y = tf32u(pa[j].y);
            ua.z = tf32u(pa[j].z); ua.w = tf32u(pa[j].w);
            ub.x = tf32u(pb[j].x); ub.y = tf32u(pb[j].y);
            ub.z = tf32u(pb[j].z); ub.w = tf32u(pb[j].w);
            *(uint4*)&sA[wb] = ua;
            *(uint4*)&sB[wb] = ub;
        }
        __syncthreads();

        // prefetch next chunk while MMAs run
        if (kc < 31) {
            const int k0 = (kc + 1) << 5;
#pragma unroll
            for (int j = 0; j < 4; j++) {
                pa[j] = *(const float4*)(A + (size_t)(m0 + rowv[j]) * Dc + k0 + (qv[j] << 2));
                pb[j] = *(const float4*)(W + (size_t)(n0 + rowv[j]) * Dc + k0 + (qv[j] << 2));
            }
        }

#pragma unroll
        for (int kt = 0; kt < 4; kt++) {
            uint32_t af[4][4];
#pragma unroll
            for (int mi = 0; mi < 4; mi++) {
                const int r  = wm * 64 + mi * 16 + g;
                const int w0 = r * GSTR + kt * 8 + t;
                af[mi][0] = sA[w0];
                af[mi][2] = sA[w0 + 4];
                af[mi][1] = sA[w0 + 8 * GSTR];
                af[mi][3] = sA[w0 + 8 * GSTR + 4];
            }
#pragma unroll
            for (int nj = 0; nj < 4; nj++) {
                const int n = wn * 32 + nj * 8 + g;
                const int w = n * GSTR + kt * 8 + t;
                const uint32_t b0 = sB[w], b1 = sB[w + 4];
#pragma unroll
                for (int mi = 0; mi < 4; mi++)
                    mma8(acc[mi][nj], af[mi], b0, b1);
            }
        }
        __syncthreads();
    }

    // Epilogue: bias + store (optionally split-head scatter)
#pragma unroll
    for (int nj = 0; nj < 4; nj++) {
        const int col = n0 + wn * 32 + nj * 8 + (t << 1);
        const float bx = bias[col], by = bias[col + 1];
#pragma unroll
        for (int mi = 0; mi < 4; mi++) {
            const int r1 = m0 + wm * 64 + mi * 16 + g;
            const int r2 = r1 + 8;
            float2 lo = make_float2(acc[mi][nj][0] + bx, acc[mi][nj][1] + by);
            float2 hi = make_float2(acc[mi][nj][2] + bx, acc[mi][nj][3] + by);
            if (split_head) {
                const int h = col >> 6, d = col & (DKc - 1);
                const int b1_ = r1 >> 11, s1 = r1 & (Sc - 1);
                const int b2_ = r2 >> 11, s2 = r2 & (Sc - 1);
                *(float2*)(C + ((size_t)(b1_ * Hc + h) * Sc + s1) * DKc + d) = lo;
                *(float2*)(C + ((size_t)(b2_ * Hc + h) * Sc + s2) * DKc + d) = hi;
            } else {
                *(float2*)(C + (size_t)r1 * Dc + col) = lo;
                *(float2*)(C + (size_t)r2 * Dc + col) = hi;
            }
        }
    }
}

// ===========================================================================
// Flash attention on mma.sync tf32.
// CTA = 64 q-rows of one (b,h); 4 warps, each one m16 band over all 64 kv.
// K/V tiles 64x64 staged row-major (stride 72 words) in smem.
// P stays in registers: C-frag -> A-frag via intra-quad shfl transform.
// ===========================================================================
#define KSTR 72

__global__ __launch_bounds__(128) void attn_mma(
    const float* __restrict__ Q, const float* __restrict__ K,
    const float* __restrict__ V, float* __restrict__ ctx)
{
    __shared__ uint32_t sK[64 * KSTR];   // 18.4 KB
    __shared__ uint32_t sV[64 * KSTR];

    const int tid  = threadIdx.x;
    const int lane = tid & 31;
    const int wid  = tid >> 5;     // 0..3
    const int g    = lane >> 2;
    const int t    = lane & 3;
    const int bh   = blockIdx.y;   // 0..31
    const int q0   = blockIdx.x << 6;

    const float* Qb = Q + (size_t)bh * Sc * DKc;
    const float* Kb = K + (size_t)bh * Sc * DKc;
    const float* Vb = V + (size_t)bh * Sc * DKc;

    const int r_lo = q0 + wid * 16 + g;
    const int r_hi = r_lo + 8;

    // Q A-frags in registers, scale 1/sqrt(64)=0.125 folded in
    uint32_t qa[8][4];
#pragma unroll
    for (int kt = 0; kt < 8; kt++) {
        const int d0 = kt * 8 + t;
        qa[kt][0] = tf32u(Qb[(size_t)r_lo * DKc + d0] * 0.125f);
        qa[kt][1] = tf32u(Qb[(size_t)r_hi * DKc + d0] * 0.125f);
        qa[kt][2] = tf32u(Qb[(size_t)r_lo * DKc + d0 + 4] * 0.125f);
        qa[kt][3] = tf32u(Qb[(size_t)r_hi * DKc + d0 + 4] * 0.125f);
    }

    float O[8][4];
#pragma unroll
    for (int jd = 0; jd < 8; jd++)
#pragma unroll
        for (int r = 0; r < 4; r++) O[jd][r] = 0.f;
    float m_lo = -1e30f, m_hi = -1e30f, l_lo = 0.f, l_hi = 0.f;

    const int base  = (lane & 28) | ((lane & 3) >> 1);  // P-transform src lane
    const bool oddp = lane & 1;

    for (int kv0 = 0; kv0 < Sc; kv0 += 64) {
        __syncthreads();   // all warps done reading previous tiles
        // stage K,V: 64x64 each; 8 float4 per thread per matrix
#pragma unroll
        for (int i = 0; i < 8; i++) {
            const int v   = tid + (i << 7);
            const int row = v >> 4;
            const int d0  = (v & 15) << 2;
            float4 kk = *(const float4*)(Kb + (size_t)(kv0 + row) * DKc + d0);
            float4 vv = *(const float4*)(Vb + (size_t)(kv0 + row) * DKc + d0);
            uint4 uk, uv;
            uk.x = tf32u(kk.x); uk.y = tf32u(kk.y); uk.z = tf32u(kk.z); uk.w = tf32u(kk.w);
            uv.x = tf32u(vv.x); uv.y = tf32u(vv.y); uv.z = tf32u(vv.z); uv.w = tf32u(vv.w);
            *(uint4*)&sK[row * KSTR + d0] = uk;
            *(uint4*)&sV[row * KSTR + d0] = uv;
        }
        __syncthreads();

        // scores: S = (Q*scale) @ K^T  (m16 x n64 per warp)
        float sc[8][4];
#pragma unroll
        for (int j = 0; j < 8; j++)
#pragma unroll
            for (int r = 0; r < 4; r++) sc[j][r] = 0.f;
#pragma unroll
        for (int kt = 0; kt < 8; kt++) {
#pragma unroll
            for (int j = 0; j < 8; j++) {
                const int w = (j * 8 + g) * KSTR + kt * 8 + t;   // K[kv][d]
                mma8(sc[j], qa[kt], sK[w], sK[w + 4]);
            }
        }

        // online softmax (rows g and g+8; quad owns a row)
        float mx_lo = -1e30f, mx_hi = -1e30f;
#pragma unroll
        for (int j = 0; j < 8; j++) {
            mx_lo = fmaxf(mx_lo, fmaxf(sc[j][0], sc[j][1]));
            mx_hi = fmaxf(mx_hi, fmaxf(sc[j][2], sc[j][3]));
        }
        mx_lo = fmaxf(mx_lo, __shfl_xor_sync(0xffffffffu, mx_lo, 1));
        mx_lo = fmaxf(mx_lo, __shfl_xor_sync(0xffffffffu, mx_lo, 2));
        mx_hi = fmaxf(mx_hi, __shfl_xor_sync(0xffffffffu, mx_hi, 1));
        mx_hi = fmaxf(mx_hi, __shfl_xor_sync(0xffffffffu, mx_hi, 2));

        const float mn_lo = fmaxf(m_lo, mx_lo);
        const float mn_hi = fmaxf(m_hi, mx_hi);
        const float f_lo  = __expf(m_lo - mn_lo);
        const float f_hi  = __expf(m_hi - mn_hi);
        m_lo = mn_lo; m_hi = mn_hi;

        float rs_lo = 0.f, rs_hi = 0.f;
#pragma unroll
        for (int j = 0; j < 8; j++) {
            sc[j][0] = __expf(sc[j][0] - mn_lo);
            sc[j][1] = __expf(sc[j][1] - mn_lo);
            sc[j][2] = __expf(sc[j][2] - mn_hi);
            sc[j][3] = __expf(sc[j][3] - mn_hi);
            rs_lo += sc[j][0] + sc[j][1];
            rs_hi += sc[j][2] + sc[j][3];
        }
        rs_lo += __shfl_xor_sync(0xffffffffu, rs_lo, 1);
        rs_lo += __shfl_xor_sync(0xffffffffu, rs_lo, 2);
        rs_hi += __shfl_xor_sync(0xffffffffu, rs_hi, 1);
        rs_hi += __shfl_xor_sync(0xffffffffu, rs_hi, 2);
        l_lo = l_lo * f_lo + rs_lo;
        l_hi = l_hi * f_hi + rs_hi;

#pragma unroll
        for (int jd = 0; jd < 8; jd++) {
            O[jd][0] *= f_lo; O[jd][1] *= f_lo;
            O[jd][2] *= f_hi; O[jd][3] *= f_hi;
        }

        // PV: transform P C-frag -> A-frag in registers, then accumulate O
#pragma unroll
        for (int j = 0; j < 8; j++) {
            uint32_t pf[4];
            {
                float e0 = __shfl_sync(0xffffffffu, sc[j][0], base);
                float o0 = __shfl_sync(0xffffffffu, sc[j][1], base);
                pf[0] = tf32u(oddp ? o0 : e0);
                float e1 = __shfl_sync(0xffffffffu, sc[j][2], base);
                float o1 = __shfl_sync(0xffffffffu, sc[j][3], base);
                pf[1] = tf32u(oddp ? o1 : e1);
                float e2 = __shfl_sync(0xffffffffu, sc[j][0], base + 2);
                float o2 = __shfl_sync(0xffffffffu, sc[j][1], base + 2);
                pf[2] = tf32u(oddp ? o2 : e2);
                float e3 = __shfl_sync(0xffffffffu, sc[j][2], base + 2);
                float o3 = __shfl_sync(0xffffffffu, sc[j][3], base + 2);
                pf[3] = tf32u(oddp ? o3 : e3);
            }
#pragma unroll
            for (int jd = 0; jd < 8; jd++) {
                const int w = (j * 8 + t) * KSTR + jd * 8 + g;   // V[kv][dk]
                mma8(O[jd], pf, sV[w], sV[w + 4 * KSTR]);
            }
        }
    }

    // epilogue: normalize, write merged-head ctx [B,S,D]
    const float inv_lo = 1.f / l_lo;
    const float inv_hi = 1.f / l_hi;
    const int b = bh >> 4, h = bh & (Hc - 1);
#pragma unroll
    for (int jd = 0; jd < 8; jd++) {
        const int col = h * DKc + jd * 8 + (t << 1);
        float2 lo = make_float2(O[jd][0] * inv_lo, O[jd][1] * inv_lo);
        float2 hi = make_float2(O[jd][2] * inv_hi, O[jd][3] * inv_hi);
        *(float2*)(ctx + (size_t)(b * Sc + r_lo) * Dc + col) = lo;
        *(float2*)(ctx + (size_t)(b * Sc + r_hi) * Dc + col) = hi;
    }
}

// ---------------------------------------------------------------------------
// Launch
// ---------------------------------------------------------------------------
extern "C" void kernel_launch(void* const* d_in, const int* in_sizes, int n_in,
                              void* d_out, int out_size)
{
    const float* query = (const float*)d_in[0];
    const float* key   = (const float*)d_in[1];
    const float* value = (const float*)d_in[2];
    const float* Wq    = (const float*)d_in[3];
    const float* bq    = (const float*)d_in[4];
    const float* Wk    = (const float*)d_in[5];
    const float* bk    = (const float*)d_in[6];
    const float* Wv    = (const float*)d_in[7];
    const float* bv    = (const float*)d_in[8];
    const float* Wo    = (const float*)d_in[9];
    const float* bo    = (const float*)d_in[10];
    float* out = (float*)d_out;

    float *qbuf, *kbuf, *vbuf, *cbuf;
    cudaGetSymbolAddress((void**)&qbuf, g_Q);
    cudaGetSymbolAddress((void**)&kbuf, g_K);
    cudaGetSymbolAddress((void**)&vbuf, g_V);
    cudaGetSymbolAddress((void**)&cbuf, g_ctx);

    dim3 ggrid(Dc / 128, Mc / 128);   // (8, 32)
    gemm_mma<<<ggrid, 256>>>(query, Wq, bq, qbuf, 1);
    gemm_mma<<<ggrid, 256>>>(key,   Wk, bk, kbuf, 1);
    gemm_mma<<<ggrid, 256>>>(value, Wv, bv, vbuf, 1);

    dim3 agrid(Sc / 64, Bc2 * Hc);    // (32, 32)
    attn_mma<<<agrid, 128>>>(qbuf, kbuf, vbuf, cbuf);

    gemm_mma<<<ggrid, 256>>>(cbuf, Wo, bo, out, 0);
}

// round 4
// speedup vs baseline: 5.6159x; 1.7708x over previous
#include <cuda_runtime.h>
#include <cuda_fp16.h>
#include <cstdint>
#include <math.h>

// Problem constants
#define Bc2  2
#define Sc   2048
#define Dc   1024
#define Hc   16
#define DKc  64
#define Mc   (Bc2*Sc)

// Scratch (fp16 intermediates)
__device__ __half g_Q[Bc2*Hc*Sc*DKc];    // [B,H,S,DK]
__device__ __half g_K[Bc2*Hc*Sc*DKc];
__device__ __half g_V[Bc2*Hc*Sc*DKc];
__device__ __half g_ctx[Bc2*Sc*Dc];      // merged-head [B,S,D]

// ---------------------------------------------------------------------------
// helpers
// ---------------------------------------------------------------------------
__device__ __forceinline__ uint32_t packh2(float lo, float hi) {
    __half2 h = __floats2half2_rn(lo, hi);   // x = lo (low 16 bits)
    return *(uint32_t*)&h;
}

// D(16x8,f32) += A(16x16,f16) * B(16x8,f16)
// A frag: a0=(g,2t..2t+1) a1=(g+8,2t..) a2=(g,2t+8..) a3=(g+8,2t+8..)
// B frag: b0=(k=2t..2t+1,n=g) b1=(k=2t+8..2t+9,n=g)
// C frag: c0=(g,2t) c1=(g,2t+1) c2=(g+8,2t) c3=(g+8,2t+1);  g=lane/4,t=lane%4
__device__ __forceinline__ void mma16(float c[4], const uint32_t a[4],
                                      uint32_t b0, uint32_t b1) {
    asm volatile(
        "mma.sync.aligned.m16n8k16.row.col.f32.f16.f16.f32 "
        "{%0,%1,%2,%3},{%4,%5,%6,%7},{%8,%9},{%0,%1,%2,%3};"
        : "+f"(c[0]), "+f"(c[1]), "+f"(c[2]), "+f"(c[3])
        : "r"(a[0]), "r"(a[1]), "r"(a[2]), "r"(a[3]), "r"(b0), "r"(b1));
}

__device__ __forceinline__ void ldmx4t(uint32_t& d0, uint32_t& d1,
                                       uint32_t& d2, uint32_t& d3, uint32_t addr) {
    asm volatile("ldmatrix.sync.aligned.m8n8.x4.trans.shared.b16 "
                 "{%0,%1,%2,%3}, [%4];"
                 : "=r"(d0), "=r"(d1), "=r"(d2), "=r"(d3) : "r"(addr));
}
__device__ __forceinline__ uint32_t smem_u32(const void* p) {
    uint32_t a;
    asm("{ .reg .u64 t; cvta.to.shared.u64 t, %1; cvt.u32.u64 %0, t; }"
        : "=r"(a) : "l"(p));
    return a;
}

// ===========================================================================
// Fused QKV projection: out = in @ W^T + b, split-head fp16 output.
// A fp32 [4096,1024], W fp32 [1024,1024]. CTA 128x128, 8 warps (2m x 4n),
// k-chunk 32 (fp16 rows, 20-word stride).
// ===========================================================================
#define GS 20   // smem row stride in 32-bit words (16 data + 4 pad)

__device__ __forceinline__ void gemm_body_f32in(
    const float* __restrict__ A, const float* __restrict__ W,
    const float* __restrict__ bias, __half* __restrict__ Ch,
    float* __restrict__ Cf, int split_head)
{
    __shared__ uint32_t sA[128 * GS];   // 10 KB
    __shared__ uint32_t sB[128 * GS];

    const int tid  = threadIdx.x;
    const int lane = tid & 31;
    const int wid  = tid >> 5;
    const int wm   = wid & 1;
    const int wn   = wid >> 1;
    const int g    = lane >> 2;
    const int t    = lane & 3;
    const int m0   = blockIdx.y << 7;
    const int n0   = blockIdx.x << 7;

    float acc[4][4][4];
#pragma unroll
    for (int mi = 0; mi < 4; mi++)
#pragma unroll
        for (int nj = 0; nj < 4; nj++)
#pragma unroll
            for (int r = 0; r < 4; r++) acc[mi][nj][r] = 0.f;

    int row_[4], q_[4];
#pragma unroll
    for (int j = 0; j < 4; j++) {
        int v = tid + (j << 8);
        row_[j] = v >> 3;   // 0..127
        q_[j]   = v & 7;    // float4 index (8 per 32-float row)
    }

    float4 pa[4], pb[4];
#pragma unroll
    for (int j = 0; j < 4; j++) {
        pa[j] = *(const float4*)(A + (size_t)(m0 + row_[j]) * Dc + (q_[j] << 2));
        pb[j] = *(const float4*)(W + (size_t)(n0 + row_[j]) * Dc + (q_[j] << 2));
    }

    for (int kc = 0; kc < 32; kc++) {
#pragma unroll
        for (int j = 0; j < 4; j++) {
            uint2 ua, ub;
            ua.x = packh2(pa[j].x, pa[j].y); ua.y = packh2(pa[j].z, pa[j].w);
            ub.x = packh2(pb[j].x, pb[j].y); ub.y = packh2(pb[j].z, pb[j].w);
            const int wb = row_[j] * GS + (q_[j] << 1);
            *(uint2*)&sA[wb] = ua;
            *(uint2*)&sB[wb] = ub;
        }
        __syncthreads();

        if (kc < 31) {
            const int k0 = (kc + 1) << 5;
#pragma unroll
            for (int j = 0; j < 4; j++) {
                pa[j] = *(const float4*)(A + (size_t)(m0 + row_[j]) * Dc + k0 + (q_[j] << 2));
                pb[j] = *(const float4*)(W + (size_t)(n0 + row_[j]) * Dc + k0 + (q_[j] << 2));
            }
        }

#pragma unroll
        for (int kt = 0; kt < 2; kt++) {
            uint32_t af[4][4];
#pragma unroll
            for (int mi = 0; mi < 4; mi++) {
                const int base = (wm * 64 + mi * 16 + g) * GS + kt * 8 + t;
                af[mi][0] = sA[base];
                af[mi][1] = sA[base + 8 * GS];
                af[mi][2] = sA[base + 4];
                af[mi][3] = sA[base + 8 * GS + 4];
            }
#pragma unroll
            for (int nj = 0; nj < 4; nj++) {
                const int wb = (wn * 32 + nj * 8 + g) * GS + kt * 8 + t;
                const uint32_t b0 = sB[wb], b1 = sB[wb + 4];
#pragma unroll
                for (int mi = 0; mi < 4; mi++)
                    mma16(acc[mi][nj], af[mi], b0, b1);
            }
        }
        __syncthreads();
    }

#pragma unroll
    for (int nj = 0; nj < 4; nj++) {
        const int col = n0 + wn * 32 + nj * 8 + (t << 1);
        const float bx = bias[col], by = bias[col + 1];
#pragma unroll
        for (int mi = 0; mi < 4; mi++) {
            const int r1 = m0 + wm * 64 + mi * 16 + g;
            const int r2 = r1 + 8;
            if (split_head) {
                const int h = col >> 6, d = col & (DKc - 1);
                const int b1_ = r1 >> 11, s1 = r1 & (Sc - 1);
                const int b2_ = r2 >> 11, s2 = r2 & (Sc - 1);
                __half2 lo = __floats2half2_rn(acc[mi][nj][0] + bx, acc[mi][nj][1] + by);
                __half2 hi = __floats2half2_rn(acc[mi][nj][2] + bx, acc[mi][nj][3] + by);
                *(__half2*)(Ch + ((size_t)(b1_ * Hc + h) * Sc + s1) * DKc + d) = lo;
                *(__half2*)(Ch + ((size_t)(b2_ * Hc + h) * Sc + s2) * DKc + d) = hi;
            } else {
                float2 lo = make_float2(acc[mi][nj][0] + bx, acc[mi][nj][1] + by);
                float2 hi = make_float2(acc[mi][nj][2] + bx, acc[mi][nj][3] + by);
                *(float2*)(Cf + (size_t)r1 * Dc + col) = lo;
                *(float2*)(Cf + (size_t)r2 * Dc + col) = hi;
            }
        }
    }
}

__global__ __launch_bounds__(256) void qkv_gemm(
    const float* __restrict__ qi, const float* __restrict__ ki, const float* __restrict__ vi,
    const float* __restrict__ Wq, const float* __restrict__ Wk, const float* __restrict__ Wv,
    const float* __restrict__ bq, const float* __restrict__ bk, const float* __restrict__ bv,
    __half* __restrict__ Qo, __half* __restrict__ Ko, __half* __restrict__ Vo)
{
    const float *A, *W, *b; __half* C;
    if (blockIdx.z == 0)      { A = qi; W = Wq; b = bq; C = Qo; }
    else if (blockIdx.z == 1) { A = ki; W = Wk; b = bk; C = Ko; }
    else                      { A = vi; W = Wv; b = bv; C = Vo; }
    gemm_body_f32in(A, W, b, C, nullptr, 1);
}

// ===========================================================================
// Output projection: out(fp32) = ctx(fp16) @ Wo^T + bo.
// ===========================================================================
__global__ __launch_bounds__(256) void out_gemm(
    const __half* __restrict__ A, const float* __restrict__ W,
    const float* __restrict__ bias, float* __restrict__ C)
{
    __shared__ uint32_t sA[128 * GS];
    __shared__ uint32_t sB[128 * GS];

    const int tid  = threadIdx.x;
    const int lane = tid & 31;
    const int wid  = tid >> 5;
    const int wm   = wid & 1;
    const int wn   = wid >> 1;
    const int g    = lane >> 2;
    const int t    = lane & 3;
    const int m0   = blockIdx.y << 7;
    const int n0   = blockIdx.x << 7;

    float acc[4][4][4];
#pragma unroll
    for (int mi = 0; mi < 4; mi++)
#pragma unroll
        for (int nj = 0; nj < 4; nj++)
#pragma unroll
            for (int r = 0; r < 4; r++) acc[mi][nj][r] = 0.f;

    // A staging: 2 uint4 per thread (128 rows x 16 words = 512 uint4)
    int rA[2], qA[2];
#pragma unroll
    for (int j = 0; j < 2; j++) {
        int v = tid + (j << 8);
        rA[j] = v >> 2; qA[j] = v & 3;
    }
    // W staging: 4 float4 per thread
    int rW[4], qW[4];
#pragma unroll
    for (int j = 0; j < 4; j++) {
        int v = tid + (j << 8);
        rW[j] = v >> 3; qW[j] = v & 7;
    }

    uint4 pa[2]; float4 pb[4];
#pragma unroll
    for (int j = 0; j < 2; j++)
        pa[j] = *(const uint4*)(A + (size_t)(m0 + rA[j]) * Dc + (qA[j] << 3));
#pragma unroll
    for (int j = 0; j < 4; j++)
        pb[j] = *(const float4*)(W + (size_t)(n0 + rW[j]) * Dc + (qW[j] << 2));

    for (int kc = 0; kc < 32; kc++) {
#pragma unroll
        for (int j = 0; j < 2; j++)
            *(uint4*)&sA[rA[j] * GS + (qA[j] << 2)] = pa[j];
#pragma unroll
        for (int j = 0; j < 4; j++) {
            uint2 ub;
            ub.x = packh2(pb[j].x, pb[j].y); ub.y = packh2(pb[j].z, pb[j].w);
            *(uint2*)&sB[rW[j] * GS + (qW[j] << 1)] = ub;
        }
        __syncthreads();

        if (kc < 31) {
            const int k0 = (kc + 1) << 5;
#pragma unroll
            for (int j = 0; j < 2; j++)
                pa[j] = *(const uint4*)(A + (size_t)(m0 + rA[j]) * Dc + k0 + (qA[j] << 3));
#pragma unroll
            for (int j = 0; j < 4; j++)
                pb[j] = *(const float4*)(W + (size_t)(n0 + rW[j]) * Dc + k0 + (qW[j] << 2));
        }

#pragma unroll
        for (int kt = 0; kt < 2; kt++) {
            uint32_t af[4][4];
#pragma unroll
            for (int mi = 0; mi < 4; mi++) {
                const int base = (wm * 64 + mi * 16 + g) * GS + kt * 8 + t;
                af[mi][0] = sA[base];
                af[mi][1] = sA[base + 8 * GS];
                af[mi][2] = sA[base + 4];
                af[mi][3] = sA[base + 8 * GS + 4];
            }
#pragma unroll
            for (int nj = 0; nj < 4; nj++) {
                const int wb = (wn * 32 + nj * 8 + g) * GS + kt * 8 + t;
                const uint32_t b0 = sB[wb], b1 = sB[wb + 4];
#pragma unroll
                for (int mi = 0; mi < 4; mi++)
                    mma16(acc[mi][nj], af[mi], b0, b1);
            }
        }
        __syncthreads();
    }

#pragma unroll
    for (int nj = 0; nj < 4; nj++) {
        const int col = n0 + wn * 32 + nj * 8 + (t << 1);
        const float bx = bias[col], by = bias[col + 1];
#pragma unroll
        for (int mi = 0; mi < 4; mi++) {
            const int r1 = m0 + wm * 64 + mi * 16 + g;
            const int r2 = r1 + 8;
            float2 lo = make_float2(acc[mi][nj][0] + bx, acc[mi][nj][1] + by);
            float2 hi = make_float2(acc[mi][nj][2] + bx, acc[mi][nj][3] + by);
            *(float2*)(C + (size_t)r1 * Dc + col) = lo;
            *(float2*)(C + (size_t)r2 * Dc + col) = hi;
        }
    }
}

// ===========================================================================
// Flash attention, fp16 mma m16n8k16.
// CTA = 64 q-rows of one (b,h); 4 warps, each warp one m16 band over 64 kv.
// K/V tiles 64x64 fp16 in smem (72-half row stride). Q in registers (scaled).
// P: C-frag -> A-frag direct (layout identity), V via ldmatrix.x4.trans.
// ===========================================================================
#define AS 36   // K/V smem row stride in 32-bit words (72 halves)

__global__ __launch_bounds__(128) void attn_mma(
    const __half* __restrict__ Q, const __half* __restrict__ K,
    const __half* __restrict__ V, __half* __restrict__ ctx)
{
    __shared__ uint32_t sK[64 * AS];   // 9.2 KB
    __shared__ uint32_t sV[64 * AS];

    const int tid  = threadIdx.x;
    const int lane = tid & 31;
    const int wid  = tid >> 5;
    const int g    = lane >> 2;
    const int t    = lane & 3;
    const int bh   = blockIdx.y;
    const int q0   = blockIdx.x << 6;

    const __half* Qb = Q + (size_t)bh * Sc * DKc;
    const __half* Kb = K + (size_t)bh * Sc * DKc;
    const __half* Vb = V + (size_t)bh * Sc * DKc;

    const int r_lo = q0 + wid * 16 + g;
    const int r_hi = r_lo + 8;

    // Q A-frags (scale 0.125 folded in — exact power of 2)
    uint32_t qa[4][4];
    {
        const __half2 sc2 = __float2half2_rn(0.125f);
#pragma unroll
        for (int kt = 0; kt < 4; kt++) {
            const int d0 = kt * 16 + 2 * t;
            __half2 a0 = __hmul2(*(const __half2*)(Qb + (size_t)r_lo * DKc + d0), sc2);
            __half2 a1 = __hmul2(*(const __half2*)(Qb + (size_t)r_hi * DKc + d0), sc2);
            __half2 a2 = __hmul2(*(const __half2*)(Qb + (size_t)r_lo * DKc + d0 + 8), sc2);
            __half2 a3 = __hmul2(*(const __half2*)(Qb + (size_t)r_hi * DKc + d0 + 8), sc2);
            qa[kt][0] = *(uint32_t*)&a0; qa[kt][1] = *(uint32_t*)&a1;
            qa[kt][2] = *(uint32_t*)&a2; qa[kt][3] = *(uint32_t*)&a3;
        }
    }

    // ldmatrix base address for V b-frags
    const uint32_t sVb = smem_u32(sV);
    const uint32_t vaddr0 = sVb
        + (uint32_t)(((lane & 7) + ((lane >> 3) & 1) * 8) * 144)  // row*144B
        + (uint32_t)(((lane >> 4) & 1) * 16);                      // +8 cols

    float O[8][4];
#pragma unroll
    for (int jd = 0; jd < 8; jd++)
#pragma unroll
        for (int r = 0; r < 4; r++) O[jd][r] = 0.f;
    float m_lo = -1e30f, m_hi = -1e30f, l_lo = 0.f, l_hi = 0.f;

    for (int kv0 = 0; kv0 < Sc; kv0 += 64) {
        __syncthreads();
        // stage K,V: 64 rows x 64 halves each; 4 uint4 per thread per matrix
#pragma unroll
        for (int i = 0; i < 4; i++) {
            const int v   = tid + (i << 7);
            const int row = v >> 3;
            const int q   = v & 7;
            uint4 kk = *(const uint4*)(Kb + (size_t)(kv0 + row) * DKc + (q << 3));
            uint4 vv = *(const uint4*)(Vb + (size_t)(kv0 + row) * DKc + (q << 3));
            *(uint4*)&sK[row * AS + (q << 2)] = kk;
            *(uint4*)&sV[row * AS + (q << 2)] = vv;
        }
        __syncthreads();

        // scores: S = (Q/8) @ K^T  (m16 x n64), b-frags contiguous LDS.32
        float sc[8][4];
#pragma unroll
        for (int j = 0; j < 8; j++)
#pragma unroll
            for (int r = 0; r < 4; r++) sc[j][r] = 0.f;
#pragma unroll
        for (int kt = 0; kt < 4; kt++) {
#pragma unroll
            for (int j = 0; j < 8; j++) {
                const int wb = (j * 8 + g) * AS + kt * 8 + t;
                mma16(sc[j], qa[kt], sK[wb], sK[wb + 4]);
            }
        }

        // online softmax
        float mx_lo = -1e30f, mx_hi = -1e30f;
#pragma unroll
        for (int j = 0; j < 8; j++) {
            mx_lo = fmaxf(mx_lo, fmaxf(sc[j][0], sc[j][1]));
            mx_hi = fmaxf(mx_hi, fmaxf(sc[j][2], sc[j][3]));
        }
        mx_lo = fmaxf(mx_lo, __shfl_xor_sync(0xffffffffu, mx_lo, 1));
        mx_lo = fmaxf(mx_lo, __shfl_xor_sync(0xffffffffu, mx_lo, 2));
        mx_hi = fmaxf(mx_hi, __shfl_xor_sync(0xffffffffu, mx_hi, 1));
        mx_hi = fmaxf(mx_hi, __shfl_xor_sync(0xffffffffu, mx_hi, 2));

        const float mn_lo = fmaxf(m_lo, mx_lo);
        const float mn_hi = fmaxf(m_hi, mx_hi);
        const float f_lo  = __expf(m_lo - mn_lo);
        const float f_hi  = __expf(m_hi - mn_hi);
        m_lo = mn_lo; m_hi = mn_hi;

        float rs_lo = 0.f, rs_hi = 0.f;
#pragma unroll
        for (int j = 0; j < 8; j++) {
            sc[j][0] = __expf(sc[j][0] - mn_lo);
            sc[j][1] = __expf(sc[j][1] - mn_lo);
            sc[j][2] = __expf(sc[j][2] - mn_hi);
            sc[j][3] = __expf(sc[j][3] - mn_hi);
            rs_lo += sc[j][0] + sc[j][1];
            rs_hi += sc[j][2] + sc[j][3];
        }
        rs_lo += __shfl_xor_sync(0xffffffffu, rs_lo, 1);
        rs_lo += __shfl_xor_sync(0xffffffffu, rs_lo, 2);
        rs_hi += __shfl_xor_sync(0xffffffffu, rs_hi, 1);
        rs_hi += __shfl_xor_sync(0xffffffffu, rs_hi, 2);
        l_lo = l_lo * f_lo + rs_lo;
        l_hi = l_hi * f_hi + rs_hi;

#pragma unroll
        for (int jd = 0; jd < 8; jd++) {
            O[jd][0] *= f_lo; O[jd][1] *= f_lo;
            O[jd][2] *= f_hi; O[jd][3] *= f_hi;
        }

        // PV: P C-frags map directly onto A-frags (f16 k16 identity)
#pragma unroll
        for (int u = 0; u < 4; u++) {
            uint32_t pf[4];
            pf[0] = packh2(sc[2*u][0],   sc[2*u][1]);
            pf[1] = packh2(sc[2*u][2],   sc[2*u][3]);
            pf[2] = packh2(sc[2*u+1][0], sc[2*u+1][1]);
            pf[3] = packh2(sc[2*u+1][2], sc[2*u+1][3]);
#pragma unroll
            for (int cg = 0; cg < 4; cg++) {
                uint32_t d0, d1, d2, d3;
                ldmx4t(d0, d1, d2, d3, vaddr0 + (uint32_t)(u * 2304 + cg * 32));
                mma16(O[2*cg],     pf, d0, d1);
                mma16(O[2*cg + 1], pf, d2, d3);
            }
        }
    }

    // epilogue: normalize, write merged-head ctx [B,S,D] fp16
    const float inv_lo = 1.f / l_lo;
    const float inv_hi = 1.f / l_hi;
    const int b = bh >> 4, h = bh & (Hc - 1);
#pragma unroll
    for (int jd = 0; jd < 8; jd++) {
        const int col = h * DKc + jd * 8 + (t << 1);
        __half2 lo = __floats2half2_rn(O[jd][0] * inv_lo, O[jd][1] * inv_lo);
        __half2 hi = __floats2half2_rn(O[jd][2] * inv_hi, O[jd][3] * inv_hi);
        *(__half2*)(ctx + (size_t)(b * Sc + r_lo) * Dc + col) = lo;
        *(__half2*)(ctx + (size_t)(b * Sc + r_hi) * Dc + col) = hi;
    }
}

// ---------------------------------------------------------------------------
// Launch
// ---------------------------------------------------------------------------
extern "C" void kernel_launch(void* const* d_in, const int* in_sizes, int n_in,
                              void* d_out, int out_size)
{
    const float* query = (const float*)d_in[0];
    const float* key   = (const float*)d_in[1];
    const float* value = (const float*)d_in[2];
    const float* Wq    = (const float*)d_in[3];
    const float* bq    = (const float*)d_in[4];
    const float* Wk    = (const float*)d_in[5];
    const float* bk    = (const float*)d_in[6];
    const float* Wv    = (const float*)d_in[7];
    const float* bv    = (const float*)d_in[8];
    const float* Wo    = (const float*)d_in[9];
    const float* bo    = (const float*)d_in[10];
    float* out = (float*)d_out;

    __half *qbuf, *kbuf, *vbuf, *cbuf;
    cudaGetSymbolAddress((void**)&qbuf, g_Q);
    cudaGetSymbolAddress((void**)&kbuf, g_K);
    cudaGetSymbolAddress((void**)&vbuf, g_V);
    cudaGetSymbolAddress((void**)&cbuf, g_ctx);

    dim3 qgrid(Dc / 128, Mc / 128, 3);   // (8, 32, 3)
    qkv_gemm<<<qgrid, 256>>>(query, key, value, Wq, Wk, Wv, bq, bk, bv,
                             qbuf, kbuf, vbuf);

    dim3 agrid(Sc / 64, Bc2 * Hc);       // (32, 32)
    attn_mma<<<agrid, 128>>>(qbuf, kbuf, vbuf, cbuf);

    dim3 ogrid(Dc / 128, Mc / 128);      // (8, 32)
    out_gemm<<<ogrid, 256>>>(cbuf, Wo, bo, out);
}

// round 5
// speedup vs baseline: 6.8578x; 1.2211x over previous
#include <cuda_runtime.h>
#include <cuda_fp16.h>
#include <cstdint>
#include <math.h>

// Problem constants
#define Bc2  2
#define Sc   2048
#define Dc   1024
#define Hc   16
#define DKc  64
#define Mc   (Bc2*Sc)

// Scratch (allocation-free rule: __device__ globals)
__device__ __half g_inh[3u*Mc*Dc];       // q,k,v inputs as fp16
__device__ __half g_wh[4u*Dc*Dc];        // Wq,Wk,Wv,Wo as fp16
__device__ __half g_Q[Bc2*Hc*Sc*DKc];    // [B,H,S,DK]
__device__ __half g_K[Bc2*Hc*Sc*DKc];
__device__ __half g_V[Bc2*Hc*Sc*DKc];
__device__ __half g_ctx[Bc2*Sc*Dc];      // merged-head [B,S,D]

// ---------------------------------------------------------------------------
// helpers
// ---------------------------------------------------------------------------
__device__ __forceinline__ uint32_t packh2(float lo, float hi) {
    __half2 h = __floats2half2_rn(lo, hi);
    return *(uint32_t*)&h;
}
__device__ __forceinline__ uint32_t smem_u32(const void* p) {
    uint32_t a;
    asm("{ .reg .u64 t; cvta.to.shared.u64 t, %1; cvt.u32.u64 %0, t; }"
        : "=r"(a) : "l"(p));
    return a;
}
__device__ __forceinline__ void mma16(float c[4], const uint32_t a[4],
                                      uint32_t b0, uint32_t b1) {
    asm volatile(
        "mma.sync.aligned.m16n8k16.row.col.f32.f16.f16.f32 "
        "{%0,%1,%2,%3},{%4,%5,%6,%7},{%8,%9},{%0,%1,%2,%3};"
        : "+f"(c[0]), "+f"(c[1]), "+f"(c[2]), "+f"(c[3])
        : "r"(a[0]), "r"(a[1]), "r"(a[2]), "r"(a[3]), "r"(b0), "r"(b1));
}
#define LDMX4(r0, r1, r2, r3, addr) \
    asm volatile("ldmatrix.sync.aligned.m8n8.x4.shared.b16 {%0,%1,%2,%3}, [%4];" \
                 : "=r"(r0), "=r"(r1), "=r"(r2), "=r"(r3) : "r"(addr))
#define LDMX4T(r0, r1, r2, r3, addr) \
    asm volatile("ldmatrix.sync.aligned.m8n8.x4.trans.shared.b16 {%0,%1,%2,%3}, [%4];" \
                 : "=r"(r0), "=r"(r1), "=r"(r2), "=r"(r3) : "r"(addr))
#define CP16(dst, src) \
    asm volatile("cp.async.cg.shared.global [%0], [%1], 16;" \
                 :: "r"(dst), "l"(src) : "memory")
#define CP_COMMIT() asm volatile("cp.async.commit_group;" ::: "memory")
#define CP_WAIT0()  asm volatile("cp.async.wait_group 0;" ::: "memory")

// ===========================================================================
// fp32 -> fp16 conversion pass (query,key,value, Wq,Wk,Wv,Wo)
// ===========================================================================
__global__ __launch_bounds__(256) void cvt_fp16(
    const float* __restrict__ q, const float* __restrict__ k, const float* __restrict__ v,
    const float* __restrict__ wq, const float* __restrict__ wk,
    const float* __restrict__ wv, const float* __restrict__ wo,
    __half* __restrict__ inh, __half* __restrict__ wh)
{
    const int y = blockIdx.y;
    const float* src;
    __half* dst;
    int n;
    if (y < 3) {
        src = (y == 0) ? q : (y == 1) ? k : v;
        dst = inh + (size_t)y * Mc * Dc;
        n = Mc * Dc;
    } else {
        const int w = y - 3;
        src = (w == 0) ? wq : (w == 1) ? wk : (w == 2) ? wv : wo;
        dst = wh + (size_t)w * Dc * Dc;
        n = Dc * Dc;
    }
    const int n4 = n >> 2;
    for (int i = blockIdx.x * 256 + threadIdx.x; i < n4; i += gridDim.x * 256) {
        float4 f = ((const float4*)src)[i];
        uint2 u;
        u.x = packh2(f.x, f.y);
        u.y = packh2(f.z, f.w);
        ((uint2*)dst)[i] = u;
    }
}

// ===========================================================================
// fp16 GEMM body: C = A @ W^T + bias.  A:[M,1024] fp16, W:[1024,1024] fp16.
// CTA 128x128, 8 warps (2m x 4n), k-chunk 32, cp.async double-buffered,
// ldmatrix.x4 fragment loads.
// ===========================================================================
#define GS 20                      // smem row stride in words (16 data + 4 pad)
#define STGB (128 * GS * 4)        // stage size in bytes = 10240

__device__ __forceinline__ void hgemm_body(
    const __half* __restrict__ A, const __half* __restrict__ W,
    const float* __restrict__ bias, __half* __restrict__ Ch,
    float* __restrict__ Cf, int split_head)
{
    __shared__ uint32_t sA[2 * 128 * GS];   // 20 KB
    __shared__ uint32_t sB[2 * 128 * GS];

    const int tid  = threadIdx.x;
    const int lane = tid & 31;
    const int wid  = tid >> 5;
    const int wm   = wid & 1;
    const int wn   = wid >> 1;
    const int g    = lane >> 2;
    const int t    = lane & 3;
    const int m0   = blockIdx.y << 7;
    const int n0   = blockIdx.x << 7;

    const uint32_t sA0 = smem_u32(sA);
    const uint32_t sB0 = smem_u32(sB);

    float acc[4][4][4];
#pragma unroll
    for (int mi = 0; mi < 4; mi++)
#pragma unroll
        for (int nj = 0; nj < 4; nj++)
#pragma unroll
            for (int r = 0; r < 4; r++) acc[mi][nj][r] = 0.f;

    // cp.async staging map: 512 16B-segments per matrix; 2 per thread each
    const int srow0 = tid >> 2;          // row of segment 0 (tid + 0*256)
    const int sseg0 = tid & 3;
    const int srow1 = (tid + 256) >> 2;
    const int sseg1 = (tid + 256) & 3;

    const uint32_t dA0 = sA0 + srow0 * 80 + sseg0 * 16;
    const uint32_t dA1 = sA0 + srow1 * 80 + sseg1 * 16;
    const uint32_t dB0 = sB0 + srow0 * 80 + sseg0 * 16;
    const uint32_t dB1 = sB0 + srow1 * 80 + sseg1 * 16;
    const __half* gA0 = A + (size_t)(m0 + srow0) * Dc + sseg0 * 8;
    const __half* gA1 = A + (size_t)(m0 + srow1) * Dc + sseg1 * 8;
    const __half* gB0 = W + (size_t)(n0 + srow0) * Dc + sseg0 * 8;
    const __half* gB1 = W + (size_t)(n0 + srow1) * Dc + sseg1 * 8;

    // fragment base addresses (ldmatrix.x4)
    const uint32_t abase = sA0 + (wm * 64 + (lane & 15)) * 80 + ((lane >> 4) << 4);
    const uint32_t bbase = sB0 + (wn * 32 + (lane & 15)) * 80 + ((lane >> 4) << 4);

    // prologue: stage chunk 0
    {
        CP16(dA0, gA0); CP16(dA1, gA1);
        CP16(dB0, gB0); CP16(dB1, gB1);
        CP_COMMIT();
    }

    for (int kc = 0; kc < 32; kc++) {
        CP_WAIT0();
        __syncthreads();
        if (kc < 31) {
            const int k0 = (kc + 1) << 5;
            const uint32_t so = ((kc + 1) & 1) * STGB;
            CP16(dA0 + so, gA0 + k0); CP16(dA1 + so, gA1 + k0);
            CP16(dB0 + so, gB0 + k0); CP16(dB1 + so, gB1 + k0);
            CP_COMMIT();
        }

        const uint32_t so = (kc & 1) * STGB;
#pragma unroll
        for (int kt = 0; kt < 2; kt++) {
            uint32_t af[4][4];
#pragma unroll
            for (int mi = 0; mi < 4; mi++)
                LDMX4(af[mi][0], af[mi][1], af[mi][2], af[mi][3],
                      abase + so + mi * 1280 + kt * 32);
#pragma unroll
            for (int njp = 0; njp < 2; njp++) {
                uint32_t b0, b1, b2, b3;
                LDMX4(b0, b1, b2, b3, bbase + so + njp * 1280 + kt * 32);
#pragma unroll
                for (int mi = 0; mi < 4; mi++) {
                    mma16(acc[mi][2 * njp],     af[mi], b0, b2);
                    mma16(acc[mi][2 * njp + 1], af[mi], b1, b3);
                }
            }
        }
        __syncthreads();
    }

    // epilogue
#pragma unroll
    for (int nj = 0; nj < 4; nj++) {
        const int col = n0 + wn * 32 + nj * 8 + (t << 1);
        const float bx = bias[col], by = bias[col + 1];
#pragma unroll
        for (int mi = 0; mi < 4; mi++) {
            const int r1 = m0 + wm * 64 + mi * 16 + g;
            const int r2 = r1 + 8;
            if (split_head) {
                const int h = col >> 6, d = col & (DKc - 1);
                const int b1_ = r1 >> 11, s1 = r1 & (Sc - 1);
                const int b2_ = r2 >> 11, s2 = r2 & (Sc - 1);
                __half2 lo = __floats2half2_rn(acc[mi][nj][0] + bx, acc[mi][nj][1] + by);
                __half2 hi = __floats2half2_rn(acc[mi][nj][2] + bx, acc[mi][nj][3] + by);
                *(__half2*)(Ch + ((size_t)(b1_ * Hc + h) * Sc + s1) * DKc + d) = lo;
                *(__half2*)(Ch + ((size_t)(b2_ * Hc + h) * Sc + s2) * DKc + d) = hi;
            } else {
                float2 lo = make_float2(acc[mi][nj][0] + bx, acc[mi][nj][1] + by);
                float2 hi = make_float2(acc[mi][nj][2] + bx, acc[mi][nj][3] + by);
                *(float2*)(Cf + (size_t)r1 * Dc + col) = lo;
                *(float2*)(Cf + (size_t)r2 * Dc + col) = hi;
            }
        }
    }
}

__global__ __launch_bounds__(256, 2) void qkv_gemm(
    const __half* __restrict__ inh, const __half* __restrict__ wh,
    const float* __restrict__ bq, const float* __restrict__ bk,
    const float* __restrict__ bv,
    __half* __restrict__ Qo, __half* __restrict__ Ko, __half* __restrict__ Vo)
{
    const int z = blockIdx.z;
    const __half* A = inh + (size_t)z * Mc * Dc;
    const __half* W = wh + (size_t)z * Dc * Dc;
    const float* b  = (z == 0) ? bq : (z == 1) ? bk : bv;
    __half* C = (z == 0) ? Qo : (z == 1) ? Ko : Vo;
    hgemm_body(A, W, b, C, nullptr, 1);
}

__global__ __launch_bounds__(256, 2) void out_gemm(
    const __half* __restrict__ A, const __half* __restrict__ wh,
    const float* __restrict__ bias, float* __restrict__ C)
{
    hgemm_body(A, wh + (size_t)3 * Dc * Dc, bias, nullptr, C, 0);
}

// ===========================================================================
// Flash attention, fp16 mma m16n8k16, cp.async double-buffered K/V tiles.
// CTA = 64 q-rows of one (b,h); 4 warps; K via ldmatrix.x4, V via x4.trans.
// ===========================================================================
#define AS 36                       // K/V row stride in words (72 halves)
#define ASTGB (64 * AS * 4)         // 9216 bytes per stage

__global__ __launch_bounds__(128) void attn_mma(
    const __half* __restrict__ Q, const __half* __restrict__ K,
    const __half* __restrict__ V, __half* __restrict__ ctx)
{
    __shared__ uint32_t sK[2 * 64 * AS];   // 18.4 KB
    __shared__ uint32_t sV[2 * 64 * AS];

    const int tid  = threadIdx.x;
    const int lane = tid & 31;
    const int wid  = tid >> 5;
    const int g    = lane >> 2;
    const int t    = lane & 3;
    const int bh   = blockIdx.y;
    const int q0   = blockIdx.x << 6;

    const __half* Qb = Q + (size_t)bh * Sc * DKc;
    const __half* Kb = K + (size_t)bh * Sc * DKc;
    const __half* Vb = V + (size_t)bh * Sc * DKc;

    const uint32_t sK0 = smem_u32(sK);
    const uint32_t sV0 = smem_u32(sV);

    const int r_lo = q0 + wid * 16 + g;
    const int r_hi = r_lo + 8;

    // Q A-frags (scale 0.125 folded in — exact power of 2)
    uint32_t qa[4][4];
    {
        const __half2 sc2 = __float2half2_rn(0.125f);
#pragma unroll
        for (int kt = 0; kt < 4; kt++) {
            const int d0 = kt * 16 + 2 * t;
            __half2 a0 = __hmul2(*(const __half2*)(Qb + (size_t)r_lo * DKc + d0), sc2);
            __half2 a1 = __hmul2(*(const __half2*)(Qb + (size_t)r_hi * DKc + d0), sc2);
            __half2 a2 = __hmul2(*(const __half2*)(Qb + (size_t)r_lo * DKc + d0 + 8), sc2);
            __half2 a3 = __hmul2(*(const __half2*)(Qb + (size_t)r_hi * DKc + d0 + 8), sc2);
            qa[kt][0] = *(uint32_t*)&a0; qa[kt][1] = *(uint32_t*)&a1;
            qa[kt][2] = *(uint32_t*)&a2; qa[kt][3] = *(uint32_t*)&a3;
        }
    }

    // cp.async staging map: 512 segments per matrix, 4 per thread
    int srow[4], sseg[4];
#pragma unroll
    for (int i = 0; i < 4; i++) {
        const int s = tid + (i << 7);
        srow[i] = s >> 3;
        sseg[i] = s & 7;
    }

    // fragment bases
    const uint32_t kbase = sK0 + (lane & 15) * 144 + ((lane >> 4) << 4);
    const uint32_t vbase = sV0 + ((lane & 7) + ((lane >> 3) & 1) * 8) * 144
                               + ((lane >> 4) & 1) * 16;

    float O[8][4];
#pragma unroll
    for (int jd = 0; jd < 8; jd++)
#pragma unroll
        for (int r = 0; r < 4; r++) O[jd][r] = 0.f;
    float m_lo = -1e30f, m_hi = -1e30f, l_lo = 0.f, l_hi = 0.f;

    // prologue: stage tile 0
#pragma unroll
    for (int i = 0; i < 4; i++) {
        CP16(sK0 + srow[i] * 144 + sseg[i] * 16,
             Kb + (size_t)srow[i] * DKc + sseg[i] * 8);
        CP16(sV0 + srow[i] * 144 + sseg[i] * 16,
             Vb + (size_t)srow[i] * DKc + sseg[i] * 8);
    }
    CP_COMMIT();

    for (int it = 0; it < Sc / 64; it++) {
        CP_WAIT0();
        __syncthreads();
        if (it + 1 < Sc / 64) {
            const int kv1 = (it + 1) << 6;
            const uint32_t so = ((it + 1) & 1) * ASTGB;
#pragma unroll
            for (int i = 0; i < 4; i++) {
                CP16(sK0 + so + srow[i] * 144 + sseg[i] * 16,
                     Kb + (size_t)(kv1 + srow[i]) * DKc + sseg[i] * 8);
                CP16(sV0 + so + srow[i] * 144 + sseg[i] * 16,
                     Vb + (size_t)(kv1 + srow[i]) * DKc + sseg[i] * 8);
            }
            CP_COMMIT();
        }

        const uint32_t so = (it & 1) * ASTGB;

        // scores: S = (Q/8) @ K^T   (m16 x n64 per warp)
        float sc[8][4];
#pragma unroll
        for (int j = 0; j < 8; j++)
#pragma unroll
            for (int r = 0; r < 4; r++) sc[j][r] = 0.f;
#pragma unroll
        for (int kt = 0; kt < 4; kt++) {
#pragma unroll
            for (int jp = 0; jp < 4; jp++) {
                uint32_t b0, b1, b2, b3;
                LDMX4(b0, b1, b2, b3, kbase + so + jp * 2304 + kt * 32);
                mma16(sc[2 * jp],     qa[kt], b0, b2);
                mma16(sc[2 * jp + 1], qa[kt], b1, b3);
            }
        }

        // online softmax
        float mx_lo = -1e30f, mx_hi = -1e30f;
#pragma unroll
        for (int j = 0; j < 8; j++) {
            mx_lo = fmaxf(mx_lo, fmaxf(sc[j][0], sc[j][1]));
            mx_hi = fmaxf(mx_hi, fmaxf(sc[j][2], sc[j][3]));
        }
        mx_lo = fmaxf(mx_lo, __shfl_xor_sync(0xffffffffu, mx_lo, 1));
        mx_lo = fmaxf(mx_lo, __shfl_xor_sync(0xffffffffu, mx_lo, 2));
        mx_hi = fmaxf(mx_hi, __shfl_xor_sync(0xffffffffu, mx_hi, 1));
        mx_hi = fmaxf(mx_hi, __shfl_xor_sync(0xffffffffu, mx_hi, 2));

        const float mn_lo = fmaxf(m_lo, mx_lo);
        const float mn_hi = fmaxf(m_hi, mx_hi);
        const float f_lo  = __expf(m_lo - mn_lo);
        const float f_hi  = __expf(m_hi - mn_hi);
        m_lo = mn_lo; m_hi = mn_hi;

        float rs_lo = 0.f, rs_hi = 0.f;
#pragma unroll
        for (int j = 0; j < 8; j++) {
            sc[j][0] = __expf(sc[j][0] - mn_lo);
            sc[j][1] = __expf(sc[j][1] - mn_lo);
            sc[j][2] = __expf(sc[j][2] - mn_hi);
            sc[j][3] = __expf(sc[j][3] - mn_hi);
            rs_lo += sc[j][0] + sc[j][1];
            rs_hi += sc[j][2] + sc[j][3];
        }
        rs_lo += __shfl_xor_sync(0xffffffffu, rs_lo, 1);
        rs_lo += __shfl_xor_sync(0xffffffffu, rs_lo, 2);
        rs_hi += __shfl_xor_sync(0xffffffffu, rs_hi, 1);
        rs_hi += __shfl_xor_sync(0xffffffffu, rs_hi, 2);
        l_lo = l_lo * f_lo + rs_lo;
        l_hi = l_hi * f_hi + rs_hi;

#pragma unroll
        for (int jd = 0; jd < 8; jd++) {
            O[jd][0] *= f_lo; O[jd][1] *= f_lo;
            O[jd][2] *= f_hi; O[jd][3] *= f_hi;
        }

        // PV: P C-frags map directly onto A-frags (f16 k16 identity)
#pragma unroll
        for (int u = 0; u < 4; u++) {
            uint32_t pf[4];
            pf[0] = packh2(sc[2*u][0],   sc[2*u][1]);
            pf[1] = packh2(sc[2*u][2],   sc[2*u][3]);
            pf[2] = packh2(sc[2*u+1][0], sc[2*u+1][1]);
            pf[3] = packh2(sc[2*u+1][2], sc[2*u+1][3]);
#pragma unroll
            for (int cg = 0; cg < 4; cg++) {
                uint32_t d0, d1, d2, d3;
                LDMX4T(d0, d1, d2, d3, vbase + so + (uint32_t)(u * 2304 + cg * 32));
                mma16(O[2*cg],     pf, d0, d1);
                mma16(O[2*cg + 1], pf, d2, d3);
            }
        }
        __syncthreads();
    }

    // epilogue: normalize, write merged-head ctx [B,S,D] fp16
    const float inv_lo = 1.f / l_lo;
    const float inv_hi = 1.f / l_hi;
    const int b = bh >> 4, h = bh & (Hc - 1);
#pragma unroll
    for (int jd = 0; jd < 8; jd++) {
        const int col = h * DKc + jd * 8 + (t << 1);
        __half2 lo = __floats2half2_rn(O[jd][0] * inv_lo, O[jd][1] * inv_lo);
        __half2 hi = __floats2half2_rn(O[jd][2] * inv_hi, O[jd][3] * inv_hi);
        *(__half2*)(ctx + (size_t)(b * Sc + r_lo) * Dc + col) = lo;
        *(__half2*)(ctx + (size_t)(b * Sc + r_hi) * Dc + col) = hi;
    }
}

// ---------------------------------------------------------------------------
// Launch
// ---------------------------------------------------------------------------
extern "C" void kernel_launch(void* const* d_in, const int* in_sizes, int n_in,
                              void* d_out, int out_size)
{
    const float* query = (const float*)d_in[0];
    const float* key   = (const float*)d_in[1];
    const float* value = (const float*)d_in[2];
    const float* Wq    = (const float*)d_in[3];
    const float* bq    = (const float*)d_in[4];
    const float* Wk    = (const float*)d_in[5];
    const float* bk    = (const float*)d_in[6];
    const float* Wv    = (const float*)d_in[7];
    const float* bv    = (const float*)d_in[8];
    const float* Wo    = (const float*)d_in[9];
    const float* bo    = (const float*)d_in[10];
    float* out = (float*)d_out;

    __half *inh, *wh, *qbuf, *kbuf, *vbuf, *cbuf;
    cudaGetSymbolAddress((void**)&inh,  g_inh);
    cudaGetSymbolAddress((void**)&wh,   g_wh);
    cudaGetSymbolAddress((void**)&qbuf, g_Q);
    cudaGetSymbolAddress((void**)&kbuf, g_K);
    cudaGetSymbolAddress((void**)&vbuf, g_V);
    cudaGetSymbolAddress((void**)&cbuf, g_ctx);

    cvt_fp16<<<dim3(256, 7), 256>>>(query, key, value, Wq, Wk, Wv, Wo, inh, wh);

    dim3 qgrid(Dc / 128, Mc / 128, 3);   // (8, 32, 3)
    qkv_gemm<<<qgrid, 256>>>(inh, wh, bq, bk, bv, qbuf, kbuf, vbuf);

    dim3 agrid(Sc / 64, Bc2 * Hc);       // (32, 32)
    attn_mma<<<agrid, 128>>>(qbuf, kbuf, vbuf, cbuf);

    dim3 ogrid(Dc / 128, Mc / 128);      // (8, 32)
    out_gemm<<<ogrid, 256>>>(cbuf, wh, bo, out);
}

// round 6
// speedup vs baseline: 7.3332x; 1.0693x over previous
#include <cuda_runtime.h>
#include <cuda_fp16.h>
#include <cstdint>
#include <math.h>

// Problem constants
#define Bc2  2
#define Sc   2048
#define Dc   1024
#define Hc   16
#define DKc  64
#define Mc   (Bc2*Sc)

// Scratch (allocation-free rule: __device__ globals)
__device__ __half g_inh[3u*Mc*Dc];       // q,k,v inputs as fp16
__device__ __half g_wh[4u*Dc*Dc];        // Wq,Wk,Wv,Wo as fp16
__device__ __half g_Q[Bc2*Hc*Sc*DKc];    // [B,H,S,DK]
__device__ __half g_K[Bc2*Hc*Sc*DKc];
__device__ __half g_V[Bc2*Hc*Sc*DKc];
__device__ __half g_ctx[Bc2*Sc*Dc];      // merged-head [B,S,D]

// ---------------------------------------------------------------------------
// helpers
// ---------------------------------------------------------------------------
__device__ __forceinline__ uint32_t packh2(float lo, float hi) {
    __half2 h = __floats2half2_rn(lo, hi);
    return *(uint32_t*)&h;
}
__device__ __forceinline__ uint32_t smem_u32(const void* p) {
    uint32_t a;
    asm("{ .reg .u64 t; cvta.to.shared.u64 t, %1; cvt.u32.u64 %0, t; }"
        : "=r"(a) : "l"(p));
    return a;
}
__device__ __forceinline__ void mma16(float c[4], const uint32_t a[4],
                                      uint32_t b0, uint32_t b1) {
    asm volatile(
        "mma.sync.aligned.m16n8k16.row.col.f32.f16.f16.f32 "
        "{%0,%1,%2,%3},{%4,%5,%6,%7},{%8,%9},{%0,%1,%2,%3};"
        : "+f"(c[0]), "+f"(c[1]), "+f"(c[2]), "+f"(c[3])
        : "r"(a[0]), "r"(a[1]), "r"(a[2]), "r"(a[3]), "r"(b0), "r"(b1));
}
#define LDMX4(r0, r1, r2, r3, addr) \
    asm volatile("ldmatrix.sync.aligned.m8n8.x4.shared.b16 {%0,%1,%2,%3}, [%4];" \
                 : "=r"(r0), "=r"(r1), "=r"(r2), "=r"(r3) : "r"(addr))
#define LDMX4T(r0, r1, r2, r3, addr) \
    asm volatile("ldmatrix.sync.aligned.m8n8.x4.trans.shared.b16 {%0,%1,%2,%3}, [%4];" \
                 : "=r"(r0), "=r"(r1), "=r"(r2), "=r"(r3) : "r"(addr))
#define CP16(dst, src) \
    asm volatile("cp.async.cg.shared.global [%0], [%1], 16;" \
                 :: "r"(dst), "l"(src) : "memory")
#define CP_COMMIT() asm volatile("cp.async.commit_group;" ::: "memory")
#define CP_WAIT0()  asm volatile("cp.async.wait_group 0;" ::: "memory")
#define CP_WAIT1()  asm volatile("cp.async.wait_group 1;" ::: "memory")

// ===========================================================================
// fp32 -> fp16 conversion pass (query,key,value, Wq,Wk,Wv,Wo)
// ===========================================================================
__global__ __launch_bounds__(256) void cvt_fp16(
    const float* __restrict__ q, const float* __restrict__ k, const float* __restrict__ v,
    const float* __restrict__ wq, const float* __restrict__ wk,
    const float* __restrict__ wv, const float* __restrict__ wo,
    __half* __restrict__ inh, __half* __restrict__ wh)
{
    const int y = blockIdx.y;
    const float* src;
    __half* dst;
    int n;
    if (y < 3) {
        src = (y == 0) ? q : (y == 1) ? k : v;
        dst = inh + (size_t)y * Mc * Dc;
        n = Mc * Dc;
    } else {
        const int w = y - 3;
        src = (w == 0) ? wq : (w == 1) ? wk : (w == 2) ? wv : wo;
        dst = wh + (size_t)w * Dc * Dc;
        n = Dc * Dc;
    }
    const int n4 = n >> 2;
    for (int i = blockIdx.x * 256 + threadIdx.x; i < n4; i += gridDim.x * 256) {
        float4 f = ((const float4*)src)[i];
        uint2 u;
        u.x = packh2(f.x, f.y);
        u.y = packh2(f.z, f.w);
        ((uint2*)dst)[i] = u;
    }
}

// ===========================================================================
// fp16 GEMM body: C = A @ W^T + bias.  A:[M,1024] fp16, W:[1024,1024] fp16.
// CTA 128x128, 8 warps (2m x 4n), k-chunk 32, 3-stage cp.async pipeline,
// XOR-swizzled 64B rows (zero padding), ldmatrix.x4.
// ===========================================================================
#define GS 16                       // words per row (64 bytes, no pad)
#define STGB (128 * GS * 4)         // 8192 bytes per matrix-stage

__device__ __forceinline__ void hgemm_body(
    const __half* __restrict__ A, const __half* __restrict__ W,
    const float* __restrict__ bias, __half* __restrict__ Ch,
    float* __restrict__ Cf, int split_head)
{
    __shared__ uint32_t sA[3 * 128 * GS];   // 24 KB
    __shared__ uint32_t sB[3 * 128 * GS];   // 24 KB  (total = 48 KB static)

    const int tid  = threadIdx.x;
    const int lane = tid & 31;
    const int wid  = tid >> 5;
    const int wm   = wid & 1;
    const int wn   = wid >> 1;
    const int g    = lane >> 2;
    const int t    = lane & 3;
    const int m0   = blockIdx.y << 7;
    const int n0   = blockIdx.x << 7;

    const uint32_t sA0 = smem_u32(sA);
    const uint32_t sB0 = smem_u32(sB);

    float acc[4][4][4];
#pragma unroll
    for (int mi = 0; mi < 4; mi++)
#pragma unroll
        for (int nj = 0; nj < 4; nj++)
#pragma unroll
            for (int r = 0; r < 4; r++) acc[mi][nj][r] = 0.f;

    // cp.async staging map: 512 16B segments per matrix-stage; 2 per thread
    const int row0 = tid >> 2,        ch0 = tid & 3;
    const int row1 = (tid + 256) >> 2, ch1 = (tid + 256) & 3;
    const uint32_t dA0 = sA0 + row0 * 64 + ((ch0 ^ ((row0 >> 1) & 3)) << 4);
    const uint32_t dA1 = sA0 + row1 * 64 + ((ch1 ^ ((row1 >> 1) & 3)) << 4);
    const uint32_t dB0 = sB0 + row0 * 64 + ((ch0 ^ ((row0 >> 1) & 3)) << 4);
    const uint32_t dB1 = sB0 + row1 * 64 + ((ch1 ^ ((row1 >> 1) & 3)) << 4);
    const __half* gA0 = A + (size_t)(m0 + row0) * Dc + ch0 * 8;
    const __half* gA1 = A + (size_t)(m0 + row1) * Dc + ch1 * 8;
    const __half* gB0 = W + (size_t)(n0 + row0) * Dc + ch0 * 8;
    const __half* gB1 = W + (size_t)(n0 + row1) * Dc + ch1 * 8;

    // prologue: stage chunks 0, 1
#pragma unroll
    for (int st = 0; st < 2; st++) {
        const uint32_t so = st * STGB;
        const int k0 = st << 5;
        CP16(dA0 + so, gA0 + k0); CP16(dA1 + so, gA1 + k0);
        CP16(dB0 + so, gB0 + k0); CP16(dB1 + so, gB1 + k0);
        CP_COMMIT();
    }

    // fragment bases
    const int laneq = lane & 15;
    const int rmg   = (laneq >> 1) & 3;    // row-swizzle key (same for A & B)
    const int cbit  = lane >> 4;           // 0/1
    uint32_t aRow[4], bRow[2];
#pragma unroll
    for (int mi = 0; mi < 4; mi++)
        aRow[mi] = sA0 + (wm * 64 + mi * 16 + laneq) * 64;
#pragma unroll
    for (int njp = 0; njp < 2; njp++)
        bRow[njp] = sB0 + (wn * 32 + njp * 16 + laneq) * 64;

    for (int kc = 0; kc < 32; kc++) {
        CP_WAIT1();
        __syncthreads();
        if (kc < 30) {
            const int k0 = (kc + 2) << 5;
            const uint32_t so = ((kc + 2) % 3) * STGB;
            CP16(dA0 + so, gA0 + k0); CP16(dA1 + so, gA1 + k0);
            CP16(dB0 + so, gB0 + k0); CP16(dB1 + so, gB1 + k0);
        }
        CP_COMMIT();   // empty group for tail iterations keeps wait bookkeeping

        const uint32_t so = (kc % 3) * STGB;
#pragma unroll
        for (int kt = 0; kt < 2; kt++) {
            const uint32_t c16 = (uint32_t)(((cbit + 2 * kt) ^ rmg) << 4);
            uint32_t af[4][4];
#pragma unroll
            for (int mi = 0; mi < 4; mi++)
                LDMX4(af[mi][0], af[mi][1], af[mi][2], af[mi][3],
                      aRow[mi] + so + c16);
#pragma unroll
            for (int njp = 0; njp < 2; njp++) {
                uint32_t b0, b1, b2, b3;
                LDMX4(b0, b1, b2, b3, bRow[njp] + so + c16);
#pragma unroll
                for (int mi = 0; mi < 4; mi++) {
                    mma16(acc[mi][2 * njp],     af[mi], b0, b2);
                    mma16(acc[mi][2 * njp + 1], af[mi], b1, b3);
                }
            }
        }
    }

    // epilogue
#pragma unroll
    for (int nj = 0; nj < 4; nj++) {
        const int col = n0 + wn * 32 + nj * 8 + (t << 1);
        const float bx = bias[col], by = bias[col + 1];
#pragma unroll
        for (int mi = 0; mi < 4; mi++) {
            const int r1 = m0 + wm * 64 + mi * 16 + g;
            const int r2 = r1 + 8;
            if (split_head) {
                const int h = col >> 6, d = col & (DKc - 1);
                const int b1_ = r1 >> 11, s1 = r1 & (Sc - 1);
                const int b2_ = r2 >> 11, s2 = r2 & (Sc - 1);
                __half2 lo = __floats2half2_rn(acc[mi][nj][0] + bx, acc[mi][nj][1] + by);
                __half2 hi = __floats2half2_rn(acc[mi][nj][2] + bx, acc[mi][nj][3] + by);
                *(__half2*)(Ch + ((size_t)(b1_ * Hc + h) * Sc + s1) * DKc + d) = lo;
                *(__half2*)(Ch + ((size_t)(b2_ * Hc + h) * Sc + s2) * DKc + d) = hi;
            } else {
                float2 lo = make_float2(acc[mi][nj][0] + bx, acc[mi][nj][1] + by);
                float2 hi = make_float2(acc[mi][nj][2] + bx, acc[mi][nj][3] + by);
                *(float2*)(Cf + (size_t)r1 * Dc + col) = lo;
                *(float2*)(Cf + (size_t)r2 * Dc + col) = hi;
            }
        }
    }
}

__global__ __launch_bounds__(256, 2) void qkv_gemm(
    const __half* __restrict__ inh, const __half* __restrict__ wh,
    const float* __restrict__ bq, const float* __restrict__ bk,
    const float* __restrict__ bv,
    __half* __restrict__ Qo, __half* __restrict__ Ko, __half* __restrict__ Vo)
{
    const int z = blockIdx.z;
    const __half* A = inh + (size_t)z * Mc * Dc;
    const __half* W = wh + (size_t)z * Dc * Dc;
    const float* b  = (z == 0) ? bq : (z == 1) ? bk : bv;
    __half* C = (z == 0) ? Qo : (z == 1) ? Ko : Vo;
    hgemm_body(A, W, b, C, nullptr, 1);
}

__global__ __launch_bounds__(256, 2) void out_gemm(
    const __half* __restrict__ A, const __half* __restrict__ wh,
    const float* __restrict__ bias, float* __restrict__ C)
{
    hgemm_body(A, wh + (size_t)3 * Dc * Dc, bias, nullptr, C, 0);
}

// ===========================================================================
// Flash attention, fp16 mma m16n8k16.
// CTA = 128 q-rows of one (b,h); 8 warps (one m16 band each) — K/V staging
// amortized over 2x more output. K/V rows are 128B: SW128 XOR swizzle,
// zero padding. 2-stage cp.async, one sync per kv tile.
// ===========================================================================
#define ASTGB (64 * 32 * 4)          // 8192 bytes per matrix-stage

__global__ __launch_bounds__(256) void attn_mma(
    const __half* __restrict__ Q, const __half* __restrict__ K,
    const __half* __restrict__ V, __half* __restrict__ ctx)
{
    __shared__ uint32_t sK[2 * 64 * 32];   // 16 KB
    __shared__ uint32_t sV[2 * 64 * 32];   // 16 KB

    const int tid  = threadIdx.x;
    const int lane = tid & 31;
    const int wid  = tid >> 5;     // 0..7
    const int g    = lane >> 2;
    const int t    = lane & 3;
    const int bh   = blockIdx.y;
    const int q0   = blockIdx.x << 7;

    const __half* Qb = Q + (size_t)bh * Sc * DKc;
    const __half* Kb = K + (size_t)bh * Sc * DKc;
    const __half* Vb = V + (size_t)bh * Sc * DKc;

    const uint32_t sK0 = smem_u32(sK);
    const uint32_t sV0 = smem_u32(sV);

    const int r_lo = q0 + wid * 16 + g;
    const int r_hi = r_lo + 8;

    // Q A-frags (scale 0.125 folded in — exact power of 2)
    uint32_t qa[4][4];
    {
        const __half2 sc2 = __float2half2_rn(0.125f);
#pragma unroll
        for (int kt = 0; kt < 4; kt++) {
            const int d0 = kt * 16 + 2 * t;
            __half2 a0 = __hmul2(*(const __half2*)(Qb + (size_t)r_lo * DKc + d0), sc2);
            __half2 a1 = __hmul2(*(const __half2*)(Qb + (size_t)r_hi * DKc + d0), sc2);
            __half2 a2 = __hmul2(*(const __half2*)(Qb + (size_t)r_lo * DKc + d0 + 8), sc2);
            __half2 a3 = __hmul2(*(const __half2*)(Qb + (size_t)r_hi * DKc + d0 + 8), sc2);
            qa[kt][0] = *(uint32_t*)&a0; qa[kt][1] = *(uint32_t*)&a1;
            qa[kt][2] = *(uint32_t*)&a2; qa[kt][3] = *(uint32_t*)&a3;
        }
    }

    // cp.async staging map: 512 segments per matrix-tile; 2 per thread
    const int row0 = tid >> 3,        ch0 = tid & 7;
    const int row1 = (tid + 256) >> 3, ch1 = (tid + 256) & 7;
    const uint32_t dK0 = sK0 + row0 * 128 + ((ch0 ^ (row0 & 7)) << 4);
    const uint32_t dK1 = sK0 + row1 * 128 + ((ch1 ^ (row1 & 7)) << 4);
    const uint32_t dV0 = sV0 + row0 * 128 + ((ch0 ^ (row0 & 7)) << 4);
    const uint32_t dV1 = sV0 + row1 * 128 + ((ch1 ^ (row1 & 7)) << 4);
    const __half* gK0 = Kb + (size_t)row0 * DKc + ch0 * 8;
    const __half* gK1 = Kb + (size_t)row1 * DKc + ch1 * 8;
    const __half* gV0 = Vb + (size_t)row0 * DKc + ch0 * 8;
    const __half* gV1 = Vb + (size_t)row1 * DKc + ch1 * 8;

    // fragment addressing keys
    const int laneq = lane & 15;
    const int swz   = lane & 7;            // row&7 for both K and V frag rows
    const int cbit  = lane >> 4;           // 0/1
    const uint32_t krow = (uint32_t)laneq * 128;
    const uint32_t vrow = (uint32_t)((lane & 7) + ((lane >> 3) & 1) * 8) * 128;

    float O[8][4];
#pragma unroll
    for (int jd = 0; jd < 8; jd++)
#pragma unroll
        for (int r = 0; r < 4; r++) O[jd][r] = 0.f;
    float m_lo = -1e30f, m_hi = -1e30f, l_lo = 0.f, l_hi = 0.f;

    // prologue: stage tile 0
    CP16(dK0, gK0); CP16(dK1, gK1);
    CP16(dV0, gV0); CP16(dV1, gV1);
    CP_COMMIT();

    for (int it = 0; it < Sc / 64; it++) {
        CP_WAIT0();
        __syncthreads();
        if (it + 1 < Sc / 64) {
            const int kv1 = (it + 1) << 6;
            const uint32_t so = ((it + 1) & 1) * ASTGB;
            const size_t goff = (size_t)kv1 * DKc;
            CP16(dK0 + so, gK0 + goff); CP16(dK1 + so, gK1 + goff);
            CP16(dV0 + so, gV0 + goff); CP16(dV1 + so, gV1 + goff);
            CP_COMMIT();
        }

        const uint32_t so = (it & 1) * ASTGB;

        // scores: S = (Q/8) @ K^T   (m16 x n64 per warp)
        float sc[8][4];
#pragma unroll
        for (int j = 0; j < 8; j++)
#pragma unroll
            for (int r = 0; r < 4; r++) sc[j][r] = 0.f;
#pragma unroll
        for (int kt = 0; kt < 4; kt++) {
            const uint32_t c16 = (uint32_t)(((kt * 2 + cbit) ^ swz) << 4);
#pragma unroll
            for (int jp = 0; jp < 4; jp++) {
                uint32_t b0, b1, b2, b3;
                LDMX4(b0, b1, b2, b3, sK0 + so + (uint32_t)(jp * 2048) + krow + c16);
                mma16(sc[2 * jp],     qa[kt], b0, b2);
                mma16(sc[2 * jp + 1], qa[kt], b1, b3);
            }
        }

        // online softmax
        float mx_lo = -1e30f, mx_hi = -1e30f;
#pragma unroll
        for (int j = 0; j < 8; j++) {
            mx_lo = fmaxf(mx_lo, fmaxf(sc[j][0], sc[j][1]));
            mx_hi = fmaxf(mx_hi, fmaxf(sc[j][2], sc[j][3]));
        }
        mx_lo = fmaxf(mx_lo, __shfl_xor_sync(0xffffffffu, mx_lo, 1));
        mx_lo = fmaxf(mx_lo, __shfl_xor_sync(0xffffffffu, mx_lo, 2));
        mx_hi = fmaxf(mx_hi, __shfl_xor_sync(0xffffffffu, mx_hi, 1));
        mx_hi = fmaxf(mx_hi, __shfl_xor_sync(0xffffffffu, mx_hi, 2));

        const float mn_lo = fmaxf(m_lo, mx_lo);
        const float mn_hi = fmaxf(m_hi, mx_hi);
        const float f_lo  = __expf(m_lo - mn_lo);
        const float f_hi  = __expf(m_hi - mn_hi);
        m_lo = mn_lo; m_hi = mn_hi;

        float rs_lo = 0.f, rs_hi = 0.f;
#pragma unroll
        for (int j = 0; j < 8; j++) {
            sc[j][0] = __expf(sc[j][0] - mn_lo);
            sc[j][1] = __expf(sc[j][1] - mn_lo);
            sc[j][2] = __expf(sc[j][2] - mn_hi);
            sc[j][3] = __expf(sc[j][3] - mn_hi);
            rs_lo += sc[j][0] + sc[j][1];
            rs_hi += sc[j][2] + sc[j][3];
        }
        rs_lo += __shfl_xor_sync(0xffffffffu, rs_lo, 1);
        rs_lo += __shfl_xor_sync(0xffffffffu, rs_lo, 2);
        rs_hi += __shfl_xor_sync(0xffffffffu, rs_hi, 1);
        rs_hi += __shfl_xor_sync(0xffffffffu, rs_hi, 2);
        l_lo = l_lo * f_lo + rs_lo;
        l_hi = l_hi * f_hi + rs_hi;

#pragma unroll
        for (int jd = 0; jd < 8; jd++) {
            O[jd][0] *= f_lo; O[jd][1] *= f_lo;
            O[jd][2] *= f_hi; O[jd][3] *= f_hi;
        }

        // PV: P C-frags map directly onto A-frags (f16 k16 identity)
#pragma unroll
        for (int u = 0; u < 4; u++) {
            uint32_t pf[4];
            pf[0] = packh2(sc[2*u][0],   sc[2*u][1]);
            pf[1] = packh2(sc[2*u][2],   sc[2*u][3]);
            pf[2] = packh2(sc[2*u+1][0], sc[2*u+1][1]);
            pf[3] = packh2(sc[2*u+1][2], sc[2*u+1][3]);
#pragma unroll
            for (int cg = 0; cg < 4; cg++) {
                const uint32_t c16 = (uint32_t)(((cg * 2 + cbit) ^ swz) << 4);
                uint32_t d0, d1, d2, d3;
                LDMX4T(d0, d1, d2, d3, sV0 + so + (uint32_t)(u * 2048) + vrow + c16);
                mma16(O[2*cg],     pf, d0, d1);
                mma16(O[2*cg + 1], pf, d2, d3);
            }
        }
    }

    // epilogue: normalize, write merged-head ctx [B,S,D] fp16
    const float inv_lo = 1.f / l_lo;
    const float inv_hi = 1.f / l_hi;
    const int b = bh >> 4, h = bh & (Hc - 1);
#pragma unroll
    for (int jd = 0; jd < 8; jd++) {
        const int col = h * DKc + jd * 8 + (t << 1);
        __half2 lo = __floats2half2_rn(O[jd][0] * inv_lo, O[jd][1] * inv_lo);
        __half2 hi = __floats2half2_rn(O[jd][2] * inv_hi, O[jd][3] * inv_hi);
        *(__half2*)(ctx + (size_t)(b * Sc + r_lo) * Dc + col) = lo;
        *(__half2*)(ctx + (size_t)(b * Sc + r_hi) * Dc + col) = hi;
    }
}

// ---------------------------------------------------------------------------
// Launch
// ---------------------------------------------------------------------------
extern "C" void kernel_launch(void* const* d_in, const int* in_sizes, int n_in,
                              void* d_out, int out_size)
{
    const float* query = (const float*)d_in[0];
    const float* key   = (const float*)d_in[1];
    const float* value = (const float*)d_in[2];
    const float* Wq    = (const float*)d_in[3];
    const float* bq    = (const float*)d_in[4];
    const float* Wk    = (const float*)d_in[5];
    const float* bk    = (const float*)d_in[6];
    const float* Wv    = (const float*)d_in[7];
    const float* bv    = (const float*)d_in[8];
    const float* Wo    = (const float*)d_in[9];
    const float* bo    = (const float*)d_in[10];
    float* out = (float*)d_out;

    __half *inh, *wh, *qbuf, *kbuf, *vbuf, *cbuf;
    cudaGetSymbolAddress((void**)&inh,  g_inh);
    cudaGetSymbolAddress((void**)&wh,   g_wh);
    cudaGetSymbolAddress((void**)&qbuf, g_Q);
    cudaGetSymbolAddress((void**)&kbuf, g_K);
    cudaGetSymbolAddress((void**)&vbuf, g_V);
    cudaGetSymbolAddress((void**)&cbuf, g_ctx);

    cvt_fp16<<<dim3(256, 7), 256>>>(query, key, value, Wq, Wk, Wv, Wo, inh, wh);

    dim3 qgrid(Dc / 128, Mc / 128, 3);   // (8, 32, 3)
    qkv_gemm<<<qgrid, 256>>>(inh, wh, bq, bk, bv, qbuf, kbuf, vbuf);

    dim3 agrid(Sc / 128, Bc2 * Hc);      // (16, 32)
    attn_mma<<<agrid, 256>>>(qbuf, kbuf, vbuf, cbuf);

    dim3 ogrid(Dc / 128, Mc / 128);      // (8, 32)
    out_gemm<<<ogrid, 256>>>(cbuf, wh, bo, out);
}

// round 7
// speedup vs baseline: 8.0666x; 1.1000x over previous
#include <cuda_runtime.h>
#include <cuda_fp16.h>
#include <cstdint>
#include <math.h>

// Problem constants
#define Bc2  2
#define Sc   2048
#define Dc   1024
#define Hc   16
#define DKc  64
#define Mc   (Bc2*Sc)

// Scratch (allocation-free rule: __device__ globals)
__device__ __half g_inh[3u*Mc*Dc];       // q,k,v inputs as fp16
__device__ __half g_wh[4u*Dc*Dc];        // Wq,Wk,Wv,Wo as fp16
__device__ __half g_Q[Bc2*Hc*Sc*DKc];    // [B,H,S,DK]
__device__ __half g_K[Bc2*Hc*Sc*DKc];
__device__ __half g_V[Bc2*Hc*Sc*DKc];
__device__ __half g_ctx[Bc2*Sc*Dc];      // merged-head [B,S,D]

// ---------------------------------------------------------------------------
// helpers
// ---------------------------------------------------------------------------
__device__ __forceinline__ uint32_t packh2(float lo, float hi) {
    __half2 h = __floats2half2_rn(lo, hi);
    return *(uint32_t*)&h;
}
__device__ __forceinline__ uint32_t smem_u32(const void* p) {
    uint32_t a;
    asm("{ .reg .u64 t; cvta.to.shared.u64 t, %1; cvt.u32.u64 %0, t; }"
        : "=r"(a) : "l"(p));
    return a;
}
__device__ __forceinline__ float ex2f(float x) {
    float r;
    asm("ex2.approx.ftz.f32 %0, %1;" : "=f"(r) : "f"(x));
    return r;
}
__device__ __forceinline__ void mma16(float c[4], const uint32_t a[4],
                                      uint32_t b0, uint32_t b1) {
    asm volatile(
        "mma.sync.aligned.m16n8k16.row.col.f32.f16.f16.f32 "
        "{%0,%1,%2,%3},{%4,%5,%6,%7},{%8,%9},{%0,%1,%2,%3};"
        : "+f"(c[0]), "+f"(c[1]), "+f"(c[2]), "+f"(c[3])
        : "r"(a[0]), "r"(a[1]), "r"(a[2]), "r"(a[3]), "r"(b0), "r"(b1));
}
#define LDMX4(r0, r1, r2, r3, addr) \
    asm volatile("ldmatrix.sync.aligned.m8n8.x4.shared.b16 {%0,%1,%2,%3}, [%4];" \
                 : "=r"(r0), "=r"(r1), "=r"(r2), "=r"(r3) : "r"(addr))
#define LDMX4T(r0, r1, r2, r3, addr) \
    asm volatile("ldmatrix.sync.aligned.m8n8.x4.trans.shared.b16 {%0,%1,%2,%3}, [%4];" \
                 : "=r"(r0), "=r"(r1), "=r"(r2), "=r"(r3) : "r"(addr))
#define CP16(dst, src) \
    asm volatile("cp.async.cg.shared.global [%0], [%1], 16;" \
                 :: "r"(dst), "l"(src) : "memory")
#define CP_COMMIT() asm volatile("cp.async.commit_group;" ::: "memory")
#define CP_WAIT0()  asm volatile("cp.async.wait_group 0;" ::: "memory")
#define CP_WAIT1()  asm volatile("cp.async.wait_group 1;" ::: "memory")

// ===========================================================================
// fp32 -> fp16 conversion pass (query,key,value, Wq,Wk,Wv,Wo)
// ===========================================================================
__global__ __launch_bounds__(256) void cvt_fp16(
    const float* __restrict__ q, const float* __restrict__ k, const float* __restrict__ v,
    const float* __restrict__ wq, const float* __restrict__ wk,
    const float* __restrict__ wv, const float* __restrict__ wo,
    __half* __restrict__ inh, __half* __restrict__ wh)
{
    const int y = blockIdx.y;
    const float* src;
    __half* dst;
    int n;
    if (y < 3) {
        src = (y == 0) ? q : (y == 1) ? k : v;
        dst = inh + (size_t)y * Mc * Dc;
        n = Mc * Dc;
    } else {
        const int w = y - 3;
        src = (w == 0) ? wq : (w == 1) ? wk : (w == 2) ? wv : wo;
        dst = wh + (size_t)w * Dc * Dc;
        n = Dc * Dc;
    }
    const int n4 = n >> 2;
    for (int i = blockIdx.x * 256 + threadIdx.x; i < n4; i += gridDim.x * 256) {
        float4 f = ((const float4*)src)[i];
        uint2 u;
        u.x = packh2(f.x, f.y);
        u.y = packh2(f.z, f.w);
        ((uint2*)dst)[i] = u;
    }
}

// ===========================================================================
// fp16 GEMM: C = A @ W^T + bias. CTA 128x128, 8 warps (2m x 4n),
// k-chunk 64, 2-stage cp.async in 64 KB DYNAMIC smem,
// SW128-style swizzle (seg ^= row&7) on 128B rows, ldmatrix.x4.
// ===========================================================================
#define MSTG 16384u   // bytes per matrix-stage (128 rows x 128 B)

__device__ __forceinline__ void hgemm_body(
    const __half* __restrict__ A, const __half* __restrict__ W,
    const float* __restrict__ bias, __half* __restrict__ Ch,
    float* __restrict__ Cf, int split_head)
{
    extern __shared__ uint32_t dynsm[];   // 64 KB: A s0, A s1, B s0, B s1

    const int tid  = threadIdx.x;
    const int lane = tid & 31;
    const int wid  = tid >> 5;
    const int wm   = wid & 1;
    const int wn   = wid >> 1;
    const int g    = lane >> 2;
    const int t    = lane & 3;
    const int m0   = blockIdx.y << 7;
    const int n0   = blockIdx.x << 7;

    const uint32_t sA0 = smem_u32(dynsm);
    const uint32_t sB0 = sA0 + 2 * MSTG;

    float acc[4][4][4];
#pragma unroll
    for (int mi = 0; mi < 4; mi++)
#pragma unroll
        for (int nj = 0; nj < 4; nj++)
#pragma unroll
            for (int r = 0; r < 4; r++) acc[mi][nj][r] = 0.f;

    // cp.async staging: 1024 16B-segments per matrix-stage, 4 per thread
    int rw[4], sg[4];
    uint32_t dOf[4];
#pragma unroll
    for (int i = 0; i < 4; i++) {
        const int s = tid + (i << 8);
        rw[i] = s >> 3;
        sg[i] = s & 7;
        dOf[i] = (uint32_t)(rw[i] * 128 + ((sg[i] ^ (rw[i] & 7)) << 4));
    }

    // prologue: stage chunk 0
#pragma unroll
    for (int i = 0; i < 4; i++) {
        CP16(sA0 + dOf[i], A + (size_t)(m0 + rw[i]) * Dc + sg[i] * 8);
        CP16(sB0 + dOf[i], W + (size_t)(n0 + rw[i]) * Dc + sg[i] * 8);
    }
    CP_COMMIT();

    // fragment bases
    const int laneq = lane & 15;
    const int rmg   = laneq & 7;
    const int cbit  = lane >> 4;
    uint32_t aRow[4], bRow[2];
#pragma unroll
    for (int mi = 0; mi < 4; mi++)
        aRow[mi] = sA0 + (wm * 64 + mi * 16 + laneq) * 128;
#pragma unroll
    for (int njp = 0; njp < 2; njp++)
        bRow[njp] = sB0 + (wn * 32 + njp * 16 + laneq) * 128;

    for (int kc = 0; kc < 16; kc++) {
        CP_WAIT0();
        __syncthreads();
        if (kc < 15) {   // stage chunk kc+1 into the other buffer (overlaps compute)
            const int k0 = (kc + 1) << 6;
            const uint32_t so = ((kc + 1) & 1) * MSTG;
#pragma unroll
            for (int i = 0; i < 4; i++) {
                CP16(sA0 + so + dOf[i], A + (size_t)(m0 + rw[i]) * Dc + k0 + sg[i] * 8);
                CP16(sB0 + so + dOf[i], W + (size_t)(n0 + rw[i]) * Dc + k0 + sg[i] * 8);
            }
        }
        CP_COMMIT();

        const uint32_t so = (kc & 1) * MSTG;
#pragma unroll
        for (int kt = 0; kt < 4; kt++) {
            const uint32_t c16 = (uint32_t)(((2 * kt + cbit) ^ rmg) << 4);
            uint32_t af[4][4];
#pragma unroll
            for (int mi = 0; mi < 4; mi++)
                LDMX4(af[mi][0], af[mi][1], af[mi][2], af[mi][3],
                      aRow[mi] + so + c16);
#pragma unroll
            for (int njp = 0; njp < 2; njp++) {
                uint32_t b0, b1, b2, b3;
                LDMX4(b0, b1, b2, b3, bRow[njp] + so + c16);
#pragma unroll
                for (int mi = 0; mi < 4; mi++) {
                    mma16(acc[mi][2 * njp],     af[mi], b0, b2);
                    mma16(acc[mi][2 * njp + 1], af[mi], b1, b3);
                }
            }
        }
    }

    // epilogue
#pragma unroll
    for (int nj = 0; nj < 4; nj++) {
        const int col = n0 + wn * 32 + nj * 8 + (t << 1);
        const float bx = bias[col], by = bias[col + 1];
#pragma unroll
        for (int mi = 0; mi < 4; mi++) {
            const int r1 = m0 + wm * 64 + mi * 16 + g;
            const int r2 = r1 + 8;
            if (split_head) {
                const int h = col >> 6, d = col & (DKc - 1);
                const int b1_ = r1 >> 11, s1 = r1 & (Sc - 1);
                const int b2_ = r2 >> 11, s2 = r2 & (Sc - 1);
                __half2 lo = __floats2half2_rn(acc[mi][nj][0] + bx, acc[mi][nj][1] + by);
                __half2 hi = __floats2half2_rn(acc[mi][nj][2] + bx, acc[mi][nj][3] + by);
                *(__half2*)(Ch + ((size_t)(b1_ * Hc + h) * Sc + s1) * DKc + d) = lo;
                *(__half2*)(Ch + ((size_t)(b2_ * Hc + h) * Sc + s2) * DKc + d) = hi;
            } else {
                float2 lo = make_float2(acc[mi][nj][0] + bx, acc[mi][nj][1] + by);
                float2 hi = make_float2(acc[mi][nj][2] + bx, acc[mi][nj][3] + by);
                *(float2*)(Cf + (size_t)r1 * Dc + col) = lo;
                *(float2*)(Cf + (size_t)r2 * Dc + col) = hi;
            }
        }
    }
}

__global__ __launch_bounds__(256, 2) void qkv_gemm(
    const __half* __restrict__ inh, const __half* __restrict__ wh,
    const float* __restrict__ bq, const float* __restrict__ bk,
    const float* __restrict__ bv,
    __half* __restrict__ Qo, __half* __restrict__ Ko, __half* __restrict__ Vo)
{
    const int z = blockIdx.z;
    const __half* A = inh + (size_t)z * Mc * Dc;
    const __half* W = wh + (size_t)z * Dc * Dc;
    const float* b  = (z == 0) ? bq : (z == 1) ? bk : bv;
    __half* C = (z == 0) ? Qo : (z == 1) ? Ko : Vo;
    hgemm_body(A, W, b, C, nullptr, 1);
}

__global__ __launch_bounds__(256, 2) void out_gemm(
    const __half* __restrict__ A, const __half* __restrict__ wh,
    const float* __restrict__ bias, float* __restrict__ C)
{
    hgemm_body(A, wh + (size_t)3 * Dc * Dc, bias, nullptr, C, 0);
}

// ===========================================================================
// Flash attention, fp16 mma m16n8k16, base-2 softmax (log2e folded into Q),
// 3-stage cp.async ring for K/V (48 KB static), 128 q-rows per CTA.
// ===========================================================================
#define ASTGB 8192u          // bytes per matrix-stage (64 rows x 128 B)

__global__ __launch_bounds__(256, 2) void attn_mma(
    const __half* __restrict__ Q, const __half* __restrict__ K,
    const __half* __restrict__ V, __half* __restrict__ ctx)
{
    __shared__ uint32_t sK[3 * 64 * 32];   // 24 KB
    __shared__ uint32_t sV[3 * 64 * 32];   // 24 KB

    const int tid  = threadIdx.x;
    const int lane = tid & 31;
    const int wid  = tid >> 5;     // 0..7
    const int g    = lane >> 2;
    const int t    = lane & 3;
    const int bh   = blockIdx.y;
    const int q0   = blockIdx.x << 7;

    const __half* Qb = Q + (size_t)bh * Sc * DKc;
    const __half* Kb = K + (size_t)bh * Sc * DKc;
    const __half* Vb = V + (size_t)bh * Sc * DKc;

    const uint32_t sK0 = smem_u32(sK);
    const uint32_t sV0 = smem_u32(sV);

    const int r_lo = q0 + wid * 16 + g;
    const int r_hi = r_lo + 8;

    // Q A-frags, scale = log2(e)/sqrt(64) folded in (base-2 softmax)
    uint32_t qa[4][4];
    {
        const __half2 sc2 = __float2half2_rn(0.125f * 1.4426950408889634f);
#pragma unroll
        for (int kt = 0; kt < 4; kt++) {
            const int d0 = kt * 16 + 2 * t;
            __half2 a0 = __hmul2(*(const __half2*)(Qb + (size_t)r_lo * DKc + d0), sc2);
            __half2 a1 = __hmul2(*(const __half2*)(Qb + (size_t)r_hi * DKc + d0), sc2);
            __half2 a2 = __hmul2(*(const __half2*)(Qb + (size_t)r_lo * DKc + d0 + 8), sc2);
            __half2 a3 = __hmul2(*(const __half2*)(Qb + (size_t)r_hi * DKc + d0 + 8), sc2);
            qa[kt][0] = *(uint32_t*)&a0; qa[kt][1] = *(uint32_t*)&a1;
            qa[kt][2] = *(uint32_t*)&a2; qa[kt][3] = *(uint32_t*)&a3;
        }
    }

    // cp.async staging map: 512 segments per matrix-tile; 2 per thread
    const int row0 = tid >> 3,         ch0 = tid & 7;
    const int row1 = (tid + 256) >> 3, ch1 = (tid + 256) & 7;
    const uint32_t o0 = (uint32_t)(row0 * 128 + ((ch0 ^ (row0 & 7)) << 4));
    const uint32_t o1 = (uint32_t)(row1 * 128 + ((ch1 ^ (row1 & 7)) << 4));
    const __half* gK0 = Kb + (size_t)row0 * DKc + ch0 * 8;
    const __half* gK1 = Kb + (size_t)row1 * DKc + ch1 * 8;
    const __half* gV0 = Vb + (size_t)row0 * DKc + ch0 * 8;
    const __half* gV1 = Vb + (size_t)row1 * DKc + ch1 * 8;

    // fragment addressing keys
    const int laneq = lane & 15;
    const int swz   = lane & 7;
    const int cbit  = lane >> 4;
    const uint32_t krow = (uint32_t)laneq * 128;
    const uint32_t vrow = (uint32_t)((lane & 7) + ((lane >> 3) & 1) * 8) * 128;

    float O[8][4];
#pragma unroll
    for (int jd = 0; jd < 8; jd++)
#pragma unroll
        for (int r = 0; r < 4; r++) O[jd][r] = 0.f;
    float m_lo = -1e30f, m_hi = -1e30f, l_lo = 0.f, l_hi = 0.f;

    // prologue: stage tiles 0 and 1 (separate commit groups)
#pragma unroll
    for (int st = 0; st < 2; st++) {
        const uint32_t so = st * ASTGB;
        const size_t goff = (size_t)(st << 6) * DKc;
        CP16(sK0 + so + o0, gK0 + goff); CP16(sK0 + so + o1, gK1 + goff);
        CP16(sV0 + so + o0, gV0 + goff); CP16(sV0 + so + o1, gV1 + goff);
        CP_COMMIT();
    }

    for (int it = 0; it < Sc / 64; it++) {
        CP_WAIT1();
        __syncthreads();
        if (it + 2 < Sc / 64) {
            const int kv2 = (it + 2) << 6;
            const uint32_t so = ((it + 2) % 3) * ASTGB;
            const size_t goff = (size_t)kv2 * DKc;
            CP16(sK0 + so + o0, gK0 + goff); CP16(sK0 + so + o1, gK1 + goff);
            CP16(sV0 + so + o0, gV0 + goff); CP16(sV0 + so + o1, gV1 + goff);
        }
        CP_COMMIT();

        const uint32_t so = (it % 3) * ASTGB;

        // scores: S2 = (Q*log2e/8) @ K^T   (m16 x n64 per warp)
        float sc[8][4];
#pragma unroll
        for (int j = 0; j < 8; j++)
#pragma unroll
            for (int r = 0; r < 4; r++) sc[j][r] = 0.f;
#pragma unroll
        for (int kt = 0; kt < 4; kt++) {
            const uint32_t c16 = (uint32_t)(((kt * 2 + cbit) ^ swz) << 4);
#pragma unroll
            for (int jp = 0; jp < 4; jp++) {
                uint32_t b0, b1, b2, b3;
                LDMX4(b0, b1, b2, b3, sK0 + so + (uint32_t)(jp * 2048) + krow + c16);
                mma16(sc[2 * jp],     qa[kt], b0, b2);
                mma16(sc[2 * jp + 1], qa[kt], b1, b3);
            }
        }

        // online softmax (base 2)
        float mx_lo = -1e30f, mx_hi = -1e30f;
#pragma unroll
        for (int j = 0; j < 8; j++) {
            mx_lo = fmaxf(mx_lo, fmaxf(sc[j][0], sc[j][1]));
            mx_hi = fmaxf(mx_hi, fmaxf(sc[j][2], sc[j][3]));
        }
        mx_lo = fmaxf(mx_lo, __shfl_xor_sync(0xffffffffu, mx_lo, 1));
        mx_lo = fmaxf(mx_lo, __shfl_xor_sync(0xffffffffu, mx_lo, 2));
        mx_hi = fmaxf(mx_hi, __shfl_xor_sync(0xffffffffu, mx_hi, 1));
        mx_hi = fmaxf(mx_hi, __shfl_xor_sync(0xffffffffu, mx_hi, 2));

        const float mn_lo = fmaxf(m_lo, mx_lo);
        const float mn_hi = fmaxf(m_hi, mx_hi);
        const float f_lo  = ex2f(m_lo - mn_lo);
        const float f_hi  = ex2f(m_hi - mn_hi);
        m_lo = mn_lo; m_hi = mn_hi;

        float rs_lo = 0.f, rs_hi = 0.f;
#pragma unroll
        for (int j = 0; j < 8; j++) {
            sc[j][0] = ex2f(sc[j][0] - mn_lo);
            sc[j][1] = ex2f(sc[j][1] - mn_lo);
            sc[j][2] = ex2f(sc[j][2] - mn_hi);
            sc[j][3] = ex2f(sc[j][3] - mn_hi);
            rs_lo += sc[j][0] + sc[j][1];
            rs_hi += sc[j][2] + sc[j][3];
        }
        rs_lo += __shfl_xor_sync(0xffffffffu, rs_lo, 1);
        rs_lo += __shfl_xor_sync(0xffffffffu, rs_lo, 2);
        rs_hi += __shfl_xor_sync(0xffffffffu, rs_hi, 1);
        rs_hi += __shfl_xor_sync(0xffffffffu, rs_hi, 2);
        l_lo = l_lo * f_lo + rs_lo;
        l_hi = l_hi * f_hi + rs_hi;

#pragma unroll
        for (int jd = 0; jd < 8; jd++) {
            O[jd][0] *= f_lo; O[jd][1] *= f_lo;
            O[jd][2] *= f_hi; O[jd][3] *= f_hi;
        }

        // PV: P C-frags map directly onto A-frags (f16 k16 identity)
#pragma unroll
        for (int u = 0; u < 4; u++) {
            uint32_t pf[4];
            pf[0] = packh2(sc[2*u][0],   sc[2*u][1]);
            pf[1] = packh2(sc[2*u][2],   sc[2*u][3]);
            pf[2] = packh2(sc[2*u+1][0], sc[2*u+1][1]);
            pf[3] = packh2(sc[2*u+1][2], sc[2*u+1][3]);
#pragma unroll
            for (int cg = 0; cg < 4; cg++) {
                const uint32_t c16 = (uint32_t)(((cg * 2 + cbit) ^ swz) << 4);
                uint32_t d0, d1, d2, d3;
                LDMX4T(d0, d1, d2, d3, sV0 + so + (uint32_t)(u * 2048) + vrow + c16);
                mma16(O[2*cg],     pf, d0, d1);
                mma16(O[2*cg + 1], pf, d2, d3);
            }
        }
    }

    // epilogue: normalize, write merged-head ctx [B,S,D] fp16
    const float inv_lo = 1.f / l_lo;
    const float inv_hi = 1.f / l_hi;
    const int b = bh >> 4, h = bh & (Hc - 1);
#pragma unroll
    for (int jd = 0; jd < 8; jd++) {
        const int col = h * DKc + jd * 8 + (t << 1);
        __half2 lo = __floats2half2_rn(O[jd][0] * inv_lo, O[jd][1] * inv_lo);
        __half2 hi = __floats2half2_rn(O[jd][2] * inv_hi, O[jd][3] * inv_hi);
        *(__half2*)(ctx + (size_t)(b * Sc + r_lo) * Dc + col) = lo;
        *(__half2*)(ctx + (size_t)(b * Sc + r_hi) * Dc + col) = hi;
    }
}

// ---------------------------------------------------------------------------
// Launch
// ---------------------------------------------------------------------------
#define GEMM_DYN_SMEM (4u * MSTG)   // 64 KB

extern "C" void kernel_launch(void* const* d_in, const int* in_sizes, int n_in,
                              void* d_out, int out_size)
{
    const float* query = (const float*)d_in[0];
    const float* key   = (const float*)d_in[1];
    const float* value = (const float*)d_in[2];
    const float* Wq    = (const float*)d_in[3];
    const float* bq    = (const float*)d_in[4];
    const float* Wk    = (const float*)d_in[5];
    const float* bk    = (const float*)d_in[6];
    const float* Wv    = (const float*)d_in[7];
    const float* bv    = (const float*)d_in[8];
    const float* Wo    = (const float*)d_in[9];
    const float* bo    = (const float*)d_in[10];
    float* out = (float*)d_out;

    __half *inh, *wh, *qbuf, *kbuf, *vbuf, *cbuf;
    cudaGetSymbolAddress((void**)&inh,  g_inh);
    cudaGetSymbolAddress((void**)&wh,   g_wh);
    cudaGetSymbolAddress((void**)&qbuf, g_Q);
    cudaGetSymbolAddress((void**)&kbuf, g_K);
    cudaGetSymbolAddress((void**)&vbuf, g_V);
    cudaGetSymbolAddress((void**)&cbuf, g_ctx);

    // Function-attribute calls (not stream ops — graph-capture safe, idempotent)
    cudaFuncSetAttribute(qkv_gemm, cudaFuncAttributeMaxDynamicSharedMemorySize,
                         GEMM_DYN_SMEM);
    cudaFuncSetAttribute(out_gemm, cudaFuncAttributeMaxDynamicSharedMemorySize,
                         GEMM_DYN_SMEM);

    cvt_fp16<<<dim3(256, 7), 256>>>(query, key, value, Wq, Wk, Wv, Wo, inh, wh);

    dim3 qgrid(Dc / 128, Mc / 128, 3);   // (8, 32, 3)
    qkv_gemm<<<qgrid, 256, GEMM_DYN_SMEM>>>(inh, wh, bq, bk, bv, qbuf, kbuf, vbuf);

    dim3 agrid(Sc / 128, Bc2 * Hc);      // (16, 32)
    attn_mma<<<agrid, 256>>>(qbuf, kbuf, vbuf, cbuf);

    dim3 ogrid(Dc / 128, Mc / 128);      // (8, 32)
    out_gemm<<<ogrid, 256, GEMM_DYN_SMEM>>>(cbuf, wh, bo, out);
}